// round 1
// baseline (speedup 1.0000x reference)
#include <cuda_runtime.h>
#include <cstdint>

typedef unsigned long long ull;

#define D_DIM 1024
#define H_DIM 2048
#define E_NUM 8
#define T_MAX 4096
#define BM 128
#define MAX_TILES ((2 * T_MAX) / BM + E_NUM)   /* 72 */
#define MAX_ROWS  (MAX_TILES * BM)             /* 9216 */

// ---------------- device-global scratch (no runtime allocation allowed) ----
__device__ int   g_counts[E_NUM];
__device__ int   g_offsets[E_NUM + 1];
__device__ int   g_tile_expert[MAX_TILES];
__device__ int   g_list[E_NUM * T_MAX];        // packed (token<<1)|slot
__device__ float g_probs[2 * T_MAX];
__device__ int   g_gather[MAX_ROWS];           // compact row -> token (or -1 pad)
__device__ int   g_row_of[2 * T_MAX];          // (token,slot) -> compact row
__device__ float g_h[(size_t)MAX_ROWS * H_DIM];    // up-proj activations (~76MB)
__device__ float g_y[(size_t)MAX_ROWS * D_DIM];    // down-proj per-pair output (~38MB)

// ---------------- f32x2 packed-FMA helpers (sm_103a FFMA2 path) ------------
__device__ __forceinline__ ull pack2(float v) {
    ull r; asm("mov.b64 %0, {%1, %1};" : "=l"(r) : "f"(v)); return r;
}
__device__ __forceinline__ void fma2(ull& d, ull a, ull b) {
    asm("fma.rn.f32x2 %0, %1, %2, %0;" : "+l"(d) : "l"(a), "l"(b));
}
__device__ __forceinline__ float2 unpack2(ull v) {
    float2 f; asm("mov.b64 {%0, %1}, %2;" : "=f"(f.x), "=f"(f.y) : "l"(v)); return f;
}
__device__ __forceinline__ float silu_f(float v) {
    return v / (1.0f + __expf(-v));
}

// ---------------- K0: zero the expert counters ------------------------------
__global__ void init_kernel() {
    if (threadIdx.x < E_NUM) g_counts[threadIdx.x] = 0;
}

// ---------------- K1: router (one warp per token) ---------------------------
__global__ void router_kernel(const float* __restrict__ x,
                              const float* __restrict__ gw, int T) {
    int warp = blockIdx.x * (blockDim.x >> 5) + (threadIdx.x >> 5);
    int lane = threadIdx.x & 31;
    if (warp >= T) return;
    const float* xr = x + (size_t)warp * D_DIM;

    float acc[E_NUM];
#pragma unroll
    for (int e = 0; e < E_NUM; e++) acc[e] = 0.0f;

    for (int d = lane; d < D_DIM; d += 32) {
        float xv = xr[d];
#pragma unroll
        for (int e = 0; e < E_NUM; e++) acc[e] += xv * gw[e * D_DIM + d];
    }
#pragma unroll
    for (int e = 0; e < E_NUM; e++) {
#pragma unroll
        for (int off = 16; off > 0; off >>= 1)
            acc[e] += __shfl_xor_sync(0xFFFFFFFFu, acc[e], off);
    }
    if (lane == 0) {
        // top-2, lowest index wins ties (matches jax.lax.top_k)
        int e0 = 0; float s0 = acc[0];
#pragma unroll
        for (int e = 1; e < E_NUM; e++) if (acc[e] > s0) { s0 = acc[e]; e0 = e; }
        int e1 = -1; float s1 = -3.4e38f;
#pragma unroll
        for (int e = 0; e < E_NUM; e++)
            if (e != e0 && acc[e] > s1) { s1 = acc[e]; e1 = e; }
        // softmax over the two selected scores
        float x1 = __expf(s1 - s0);
        float inv = 1.0f / (1.0f + x1);
        int t = warp;
        g_probs[2 * t]     = inv;        // p0
        g_probs[2 * t + 1] = x1 * inv;   // p1
        int j0 = atomicAdd(&g_counts[e0], 1);
        g_list[e0 * T_MAX + j0] = (t << 1);
        int j1 = atomicAdd(&g_counts[e1], 1);
        g_list[e1 * T_MAX + j1] = (t << 1) | 1;
    }
}

// ---------------- K2: tile-aligned scan + tile->expert table ---------------
__global__ void scan_kernel(int m_tiles_max) {
    if (threadIdx.x != 0 || blockIdx.x != 0) return;
    int off = 0, nt = 0;
    for (int e = 0; e < E_NUM; e++) {
        g_offsets[e] = off;
        int c = g_counts[e];
        int te = (c + BM - 1) / BM;
        for (int k = 0; k < te; k++) g_tile_expert[nt++] = e;
        off += te * BM;
    }
    g_offsets[E_NUM] = off;
    for (; nt < m_tiles_max; nt++) g_tile_expert[nt] = -1;
}

// ---------------- K3: build gather / inverse row map ------------------------
__global__ void build_kernel() {
    int tile = blockIdx.x;
    int e = g_tile_expert[tile];
    int r = tile * BM + threadIdx.x;
    if (e < 0) { g_gather[r] = -1; return; }
    int j = r - g_offsets[e];
    if (j < g_counts[e]) {
        int entry = g_list[e * T_MAX + j];
        g_gather[r] = entry >> 1;
        g_row_of[entry] = r;
    } else {
        g_gather[r] = -1;
    }
}

// ---------------- K4: fused up-proj GEMM: h = silu(X W1^T) * (X W2^T) ------
// C tile 128x64, BK=16, 256 threads, 8x4 micro-tile, dual accumulators (f32x2)
__global__ void __launch_bounds__(256) gemm_up_kernel(
    const float* __restrict__ x,
    const float* __restrict__ w1,
    const float* __restrict__ w2) {
    const int e = g_tile_expert[blockIdx.y];
    if (e < 0) return;
    const int m0  = blockIdx.y * BM;
    const int bn0 = blockIdx.x * 64;

    __shared__ float As2[16][260];   // A rows duplicated as f32 pairs
    __shared__ float Bs1[16][68];
    __shared__ float Bs2[16][68];

    const int tid  = threadIdx.x;
    const int tm   = tid >> 4;       // 0..15
    const int tn   = tid & 15;       // 0..15
    const int lrow = tid >> 2;       // 0..63
    const int lk4  = (tid & 3) * 4;  // 0,4,8,12

    const int tokA = g_gather[m0 + lrow];
    const int tokB = g_gather[m0 + 64 + lrow];
    const float* pa0 = (tokA >= 0) ? (x + (size_t)tokA * D_DIM + lk4) : 0;
    const float* pa1 = (tokB >= 0) ? (x + (size_t)tokB * D_DIM + lk4) : 0;
    const float* pb1 = w1 + ((size_t)e * H_DIM + bn0 + lrow) * D_DIM + lk4;
    const float* pb2 = w2 + ((size_t)e * H_DIM + bn0 + lrow) * D_DIM + lk4;

    ull acc1[8][2], acc2[8][2];
#pragma unroll
    for (int i = 0; i < 8; i++) {
        acc1[i][0] = acc1[i][1] = 0ull;
        acc2[i][0] = acc2[i][1] = 0ull;
    }

    float4 ra0 = pa0 ? *(const float4*)pa0 : make_float4(0, 0, 0, 0);
    float4 ra1 = pa1 ? *(const float4*)pa1 : make_float4(0, 0, 0, 0);
    float4 rb1 = *(const float4*)pb1;
    float4 rb2 = *(const float4*)pb2;

    const int KIT = D_DIM / 16;  // 64
    for (int kt = 0; kt < KIT; kt++) {
#pragma unroll
        for (int i = 0; i < 4; i++) {
            *(ull*)&As2[lk4 + i][2 * lrow]       = pack2((&ra0.x)[i]);
            *(ull*)&As2[lk4 + i][2 * lrow + 128] = pack2((&ra1.x)[i]);
            Bs1[lk4 + i][lrow] = (&rb1.x)[i];
            Bs2[lk4 + i][lrow] = (&rb2.x)[i];
        }
        __syncthreads();
        if (kt + 1 < KIT) {
            int o = (kt + 1) * 16;
            ra0 = pa0 ? *(const float4*)(pa0 + o) : make_float4(0, 0, 0, 0);
            ra1 = pa1 ? *(const float4*)(pa1 + o) : make_float4(0, 0, 0, 0);
            rb1 = *(const float4*)(pb1 + o);
            rb2 = *(const float4*)(pb2 + o);
        }
#pragma unroll
        for (int k = 0; k < 16; k++) {
            ulonglong2 aA = *(const ulonglong2*)&As2[k][tm * 16];
            ulonglong2 aB = *(const ulonglong2*)&As2[k][tm * 16 + 4];
            ulonglong2 aC = *(const ulonglong2*)&As2[k][tm * 16 + 8];
            ulonglong2 aD = *(const ulonglong2*)&As2[k][tm * 16 + 12];
            ulonglong2 b1 = *(const ulonglong2*)&Bs1[k][tn * 4];
            ulonglong2 b2 = *(const ulonglong2*)&Bs2[k][tn * 4];
            ull A2[8] = { aA.x, aA.y, aB.x, aB.y, aC.x, aC.y, aD.x, aD.y };
#pragma unroll
            for (int i = 0; i < 8; i++) {
                fma2(acc1[i][0], A2[i], b1.x);
                fma2(acc1[i][1], A2[i], b1.y);
                fma2(acc2[i][0], A2[i], b2.x);
                fma2(acc2[i][1], A2[i], b2.y);
            }
        }
        __syncthreads();
    }

    const int gr = m0 + tm * 8;
    const int gc = bn0 + tn * 4;
#pragma unroll
    for (int i = 0; i < 8; i++) {
        float2 u0 = unpack2(acc1[i][0]), u1 = unpack2(acc1[i][1]);
        float2 v0 = unpack2(acc2[i][0]), v1 = unpack2(acc2[i][1]);
        float4 hv;
        hv.x = silu_f(u0.x) * v0.x;
        hv.y = silu_f(u0.y) * v0.y;
        hv.z = silu_f(u1.x) * v1.x;
        hv.w = silu_f(u1.y) * v1.y;
        *(float4*)&g_h[(size_t)(gr + i) * H_DIM + gc] = hv;
    }
}

// ---------------- K5: down-proj GEMM: y = h W3^T ----------------------------
// C tile 128x128, BK=16, 256 threads, 8x8 micro-tile (f32x2)
__global__ void __launch_bounds__(256) gemm_down_kernel(
    const float* __restrict__ w3) {
    const int e = g_tile_expert[blockIdx.y];
    if (e < 0) return;
    const int m0  = blockIdx.y * BM;
    const int bn0 = blockIdx.x * 128;

    __shared__ float As2[16][260];
    __shared__ float Bs[16][132];

    const int tid  = threadIdx.x;
    const int tm   = tid >> 4;
    const int tn   = tid & 15;
    const int lrow = tid >> 2;       // 0..63
    const int lk4  = (tid & 3) * 4;

    const float* pa0 = g_h + (size_t)(m0 + lrow) * H_DIM + lk4;
    const float* pa1 = g_h + (size_t)(m0 + 64 + lrow) * H_DIM + lk4;
    const float* pb0 = w3 + ((size_t)e * D_DIM + bn0 + lrow) * H_DIM + lk4;
    const float* pb1 = w3 + ((size_t)e * D_DIM + bn0 + 64 + lrow) * H_DIM + lk4;

    ull acc[8][4];
#pragma unroll
    for (int i = 0; i < 8; i++) {
        acc[i][0] = acc[i][1] = acc[i][2] = acc[i][3] = 0ull;
    }

    float4 ra0 = *(const float4*)pa0;
    float4 ra1 = *(const float4*)pa1;
    float4 rb0 = *(const float4*)pb0;
    float4 rb1 = *(const float4*)pb1;

    const int KIT = H_DIM / 16;  // 128
    for (int kt = 0; kt < KIT; kt++) {
#pragma unroll
        for (int i = 0; i < 4; i++) {
            *(ull*)&As2[lk4 + i][2 * lrow]       = pack2((&ra0.x)[i]);
            *(ull*)&As2[lk4 + i][2 * lrow + 128] = pack2((&ra1.x)[i]);
            Bs[lk4 + i][lrow]      = (&rb0.x)[i];
            Bs[lk4 + i][lrow + 64] = (&rb1.x)[i];
        }
        __syncthreads();
        if (kt + 1 < KIT) {
            int o = (kt + 1) * 16;
            ra0 = *(const float4*)(pa0 + o);
            ra1 = *(const float4*)(pa1 + o);
            rb0 = *(const float4*)(pb0 + o);
            rb1 = *(const float4*)(pb1 + o);
        }
#pragma unroll
        for (int k = 0; k < 16; k++) {
            ulonglong2 aA = *(const ulonglong2*)&As2[k][tm * 16];
            ulonglong2 aB = *(const ulonglong2*)&As2[k][tm * 16 + 4];
            ulonglong2 aC = *(const ulonglong2*)&As2[k][tm * 16 + 8];
            ulonglong2 aD = *(const ulonglong2*)&As2[k][tm * 16 + 12];
            ulonglong2 bL = *(const ulonglong2*)&Bs[k][tn * 8];
            ulonglong2 bH = *(const ulonglong2*)&Bs[k][tn * 8 + 4];
            ull A2[8] = { aA.x, aA.y, aB.x, aB.y, aC.x, aC.y, aD.x, aD.y };
#pragma unroll
            for (int i = 0; i < 8; i++) {
                fma2(acc[i][0], A2[i], bL.x);
                fma2(acc[i][1], A2[i], bL.y);
                fma2(acc[i][2], A2[i], bH.x);
                fma2(acc[i][3], A2[i], bH.y);
            }
        }
        __syncthreads();
    }

    const int gr = m0 + tm * 8;
    const int gc = bn0 + tn * 8;
#pragma unroll
    for (int i = 0; i < 8; i++) {
        float2 a = unpack2(acc[i][0]), b = unpack2(acc[i][1]);
        float2 c = unpack2(acc[i][2]), d = unpack2(acc[i][3]);
        float4 lo = make_float4(a.x, a.y, b.x, b.y);
        float4 hi = make_float4(c.x, c.y, d.x, d.y);
        *(float4*)&g_y[(size_t)(gr + i) * D_DIM + gc]     = lo;
        *(float4*)&g_y[(size_t)(gr + i) * D_DIM + gc + 4] = hi;
    }
}

// ---------------- K6: combine: out[t] = p0*y[r0] + p1*y[r1] ----------------
__global__ void combine_kernel(float* __restrict__ out, int T) {
    const int nq = D_DIM / 4;
    int idx = blockIdx.x * blockDim.x + threadIdx.x;
    if (idx >= T * nq) return;
    int t  = idx / nq;
    int dq = idx - t * nq;
    int r0 = g_row_of[2 * t];
    int r1 = g_row_of[2 * t + 1];
    float p0 = g_probs[2 * t];
    float p1 = g_probs[2 * t + 1];
    float4 y0 = *(const float4*)&g_y[(size_t)r0 * D_DIM + dq * 4];
    float4 y1 = *(const float4*)&g_y[(size_t)r1 * D_DIM + dq * 4];
    float4 o;
    o.x = p0 * y0.x + p1 * y1.x;
    o.y = p0 * y0.y + p1 * y1.y;
    o.z = p0 * y0.z + p1 * y1.z;
    o.w = p0 * y0.w + p1 * y1.w;
    *(float4*)&out[(size_t)t * D_DIM + dq * 4] = o;
}

// ---------------- launch ----------------------------------------------------
extern "C" void kernel_launch(void* const* d_in, const int* in_sizes, int n_in,
                              void* d_out, int out_size) {
    const float* x  = (const float*)d_in[0];
    const float* gw = (const float*)d_in[1];
    const float* w1 = (const float*)d_in[2];
    const float* w2 = (const float*)d_in[3];
    const float* w3 = (const float*)d_in[4];
    float* out = (float*)d_out;

    int T = in_sizes[0] / D_DIM;           // 4096
    if (T > T_MAX) T = T_MAX;
    int m_tiles = (2 * T) / BM + E_NUM;    // 72 (fixed worst-case grid)
    if (m_tiles > MAX_TILES) m_tiles = MAX_TILES;

    init_kernel<<<1, 32>>>();
    router_kernel<<<(T + 7) / 8, 256>>>(x, gw, T);
    scan_kernel<<<1, 32>>>(m_tiles);
    build_kernel<<<m_tiles, BM>>>();
    gemm_up_kernel<<<dim3(H_DIM / 64, m_tiles), 256>>>(x, w1, w2);
    gemm_down_kernel<<<dim3(D_DIM / 128, m_tiles), 256>>>(w3);
    combine_kernel<<<(T * (D_DIM / 4) + 255) / 256, 256>>>(out, T);
}

// round 3
// speedup vs baseline: 2.3617x; 2.3617x over previous
#include <cuda_runtime.h>
#include <cuda_fp16.h>
#include <cstdint>

#define D_DIM 1024
#define H_DIM 2048
#define E_NUM 8
#define T_MAX 4096
#define BM 128
#define MAX_TILES 72
#define MAX_ROWS  (MAX_TILES * BM)

#define KA_UP (3 * D_DIM)    /* 3072: tripled-K for up GEMM  */
#define KA_DN (3 * H_DIM)    /* 6144: tripled-K for down GEMM */
#define BKW 64               /* fp16 K elems per mainloop iter (128B rows) */
#define NK_UP (KA_UP / BKW)  /* 48 */
#define NK_DN (KA_DN / BKW)  /* 96 */

// ---------------- device-global scratch ------------------------------------
__device__ int   g_counts[E_NUM];
__device__ int   g_offsets[E_NUM + 1];
__device__ int   g_tile_expert[MAX_TILES];
__device__ int   g_list[E_NUM * T_MAX];
__device__ float g_probs[2 * T_MAX];
__device__ int   g_gather[MAX_ROWS];
__device__ int   g_row_of[2 * T_MAX];
__device__ __half g_xA [(size_t)T_MAX * KA_UP];            // [hi | hi | lo]
__device__ __half g_w1A[(size_t)E_NUM * H_DIM * KA_UP];    // [hi | lo | hi]
__device__ __half g_w2A[(size_t)E_NUM * H_DIM * KA_UP];    // [hi | lo | hi]
__device__ __half g_w3A[(size_t)E_NUM * D_DIM * KA_DN];    // [hi | lo | hi]
__device__ __half g_hA [(size_t)MAX_ROWS * KA_DN];         // [hi | hi | lo]
__device__ float g_y[(size_t)MAX_ROWS * D_DIM];

// ---------------- helpers ----------------------------------------------------
__device__ __forceinline__ uint32_t smem_u32(const void* p) {
    uint32_t a;
    asm("{ .reg .u64 t; cvta.to.shared.u64 t, %1; cvt.u32.u64 %0, t; }"
        : "=r"(a) : "l"(p));
    return a;
}

__device__ __forceinline__ void ldsm4(uint32_t& r0, uint32_t& r1, uint32_t& r2,
                                      uint32_t& r3, uint32_t addr) {
    asm volatile("ldmatrix.sync.aligned.m8n8.x4.shared.b16 {%0,%1,%2,%3}, [%4];"
                 : "=r"(r0), "=r"(r1), "=r"(r2), "=r"(r3) : "r"(addr));
}

__device__ __forceinline__ void mma16816(float* c, const uint32_t* a,
                                         const uint32_t* b) {
    asm volatile(
        "mma.sync.aligned.m16n8k16.row.col.f32.f16.f16.f32 "
        "{%0,%1,%2,%3},{%4,%5,%6,%7},{%8,%9},{%0,%1,%2,%3};"
        : "+f"(c[0]), "+f"(c[1]), "+f"(c[2]), "+f"(c[3])
        : "r"(a[0]), "r"(a[1]), "r"(a[2]), "r"(a[3]), "r"(b[0]), "r"(b[1]));
}

__device__ __forceinline__ float silu_f(float v) { return v / (1.0f + __expf(-v)); }

// swizzled byte offset of 16B chunk (r, c) inside a [rows x 64 fp16] tile
__device__ __forceinline__ int sw_off(int r, int c) {
    return r * 128 + ((c ^ (r & 7)) << 4);
}

// ---------------- K0-K3: routing (validated in R1) ---------------------------
__global__ void init_kernel() {
    if (threadIdx.x < E_NUM) g_counts[threadIdx.x] = 0;
}

__global__ void router_kernel(const float* __restrict__ x,
                              const float* __restrict__ gw, int T) {
    int warp = blockIdx.x * (blockDim.x >> 5) + (threadIdx.x >> 5);
    int lane = threadIdx.x & 31;
    if (warp >= T) return;
    const float* xr = x + (size_t)warp * D_DIM;
    float acc[E_NUM];
#pragma unroll
    for (int e = 0; e < E_NUM; e++) acc[e] = 0.0f;
    for (int d = lane; d < D_DIM; d += 32) {
        float xv = xr[d];
#pragma unroll
        for (int e = 0; e < E_NUM; e++) acc[e] += xv * gw[e * D_DIM + d];
    }
#pragma unroll
    for (int e = 0; e < E_NUM; e++) {
#pragma unroll
        for (int off = 16; off > 0; off >>= 1)
            acc[e] += __shfl_xor_sync(0xFFFFFFFFu, acc[e], off);
    }
    if (lane == 0) {
        int e0 = 0; float s0 = acc[0];
#pragma unroll
        for (int e = 1; e < E_NUM; e++) if (acc[e] > s0) { s0 = acc[e]; e0 = e; }
        int e1 = -1; float s1 = -3.4e38f;
#pragma unroll
        for (int e = 0; e < E_NUM; e++)
            if (e != e0 && acc[e] > s1) { s1 = acc[e]; e1 = e; }
        float x1 = __expf(s1 - s0);
        float inv = 1.0f / (1.0f + x1);
        int t = warp;
        g_probs[2 * t] = inv;
        g_probs[2 * t + 1] = x1 * inv;
        int j0 = atomicAdd(&g_counts[e0], 1);
        g_list[e0 * T_MAX + j0] = (t << 1);
        int j1 = atomicAdd(&g_counts[e1], 1);
        g_list[e1 * T_MAX + j1] = (t << 1) | 1;
    }
}

__global__ void scan_kernel(int m_tiles_max) {
    if (threadIdx.x != 0 || blockIdx.x != 0) return;
    int off = 0, nt = 0;
    for (int e = 0; e < E_NUM; e++) {
        g_offsets[e] = off;
        int c = g_counts[e];
        int te = (c + BM - 1) / BM;
        for (int k = 0; k < te; k++) g_tile_expert[nt++] = e;
        off += te * BM;
    }
    g_offsets[E_NUM] = off;
    for (; nt < m_tiles_max; nt++) g_tile_expert[nt] = -1;
}

__global__ void build_kernel() {
    int tile = blockIdx.x;
    int e = g_tile_expert[tile];
    int r = tile * BM + threadIdx.x;
    if (e < 0) { g_gather[r] = -1; return; }
    int j = r - g_offsets[e];
    if (j < g_counts[e]) {
        int entry = g_list[e * T_MAX + j];
        g_gather[r] = entry >> 1;
        g_row_of[entry] = r;
    } else {
        g_gather[r] = -1;
    }
}

// ---------------- conversions: fp32 -> tripled fp16 split -------------------
__global__ void conv_x_kernel(const float* __restrict__ src, long total4) {
    long i = blockIdx.x * (long)blockDim.x + threadIdx.x;
    if (i >= total4) return;
    long eb = i * 4;
    long row = eb / D_DIM;
    int k = (int)(eb - row * D_DIM);
    float4 v = *(const float4*)(src + eb);
    __half2 h0 = __floats2half2_rn(v.x, v.y);
    __half2 h1 = __floats2half2_rn(v.z, v.w);
    __half2 l0 = __floats2half2_rn(v.x - __half2float(__low2half(h0)),
                                   v.y - __half2float(__high2half(h0)));
    __half2 l1 = __floats2half2_rn(v.z - __half2float(__low2half(h1)),
                                   v.w - __half2float(__high2half(h1)));
    __half* dr = g_xA + row * (size_t)KA_UP;
    uint2 hw = make_uint2(*(uint32_t*)&h0, *(uint32_t*)&h1);
    uint2 lw = make_uint2(*(uint32_t*)&l0, *(uint32_t*)&l1);
    *(uint2*)(dr + k)             = hw;
    *(uint2*)(dr + D_DIM + k)     = hw;
    *(uint2*)(dr + 2 * D_DIM + k) = lw;
}

__global__ void conv_w_kernel(const float* __restrict__ src, int which, int K, long total4) {
    long i = blockIdx.x * (long)blockDim.x + threadIdx.x;
    if (i >= total4) return;
    __half* dst = (which == 0) ? g_w1A : (which == 1) ? g_w2A : g_w3A;
    long eb = i * 4;
    long row = eb / K;
    int k = (int)(eb - row * K);
    float4 v = *(const float4*)(src + eb);
    __half2 h0 = __floats2half2_rn(v.x, v.y);
    __half2 h1 = __floats2half2_rn(v.z, v.w);
    __half2 l0 = __floats2half2_rn(v.x - __half2float(__low2half(h0)),
                                   v.y - __half2float(__high2half(h0)));
    __half2 l1 = __floats2half2_rn(v.z - __half2float(__low2half(h1)),
                                   v.w - __half2float(__high2half(h1)));
    __half* dr = dst + row * (size_t)(3 * K);
    uint2 hw = make_uint2(*(uint32_t*)&h0, *(uint32_t*)&h1);
    uint2 lw = make_uint2(*(uint32_t*)&l0, *(uint32_t*)&l1);
    *(uint2*)(dr + k)         = hw;   // hi
    *(uint2*)(dr + K + k)     = lw;   // lo
    *(uint2*)(dr + 2 * K + k) = hw;   // hi
}

// ---------------- smem layouts ------------------------------------------------
#define UA_OFF(b)  ((b) ? 16384 : 0)
#define UB1_OFF(b) (32768 + ((b) ? 8192 : 0))
#define UB2_OFF(b) (49152 + ((b) ? 8192 : 0))
#define USG_OFF    65536
#define UP_SMEM    66048
#define DA_OFF(b)  ((b) ? 16384 : 0)
#define DB_OFF(b)  (32768 + ((b) ? 16384 : 0))
#define DN_SMEM    65536

// ---------------- K4: up GEMM — u=X W1^T, v=X W2^T, h=silu(u)*v ------------
// block: 128M x 64N (both matrices), 8 warps (4m x 2n), warp 32x32 per matrix
__global__ void __launch_bounds__(256) gemm_up_mma() {
    const int e = g_tile_expert[blockIdx.y];
    if (e < 0) return;
    extern __shared__ char dsm[];
    const int tid = threadIdx.x;
    const int m0 = blockIdx.y * BM;
    const int bn0 = blockIdx.x * 64;
    const uint32_t sb = smem_u32(dsm);
    int* sg = (int*)(dsm + USG_OFF);
    if (tid < BM) sg[tid] = g_gather[m0 + tid];
    __syncthreads();

    const int lane = tid & 31, wid = tid >> 5;
    const int wm = wid & 3, wn = wid >> 2;

    // staging assignments
    int rA[4], cA[4]; const __half* aptr[4];
#pragma unroll
    for (int i = 0; i < 4; i++) {
        int idx = tid + i * 256; rA[i] = idx >> 3; cA[i] = idx & 7;
        int tok = sg[rA[i]];
        aptr[i] = (tok >= 0) ? g_xA + (size_t)tok * KA_UP + cA[i] * 8 : (const __half*)0;
    }
    int rB[2], cB[2]; const __half *b1p[2], *b2p[2];
#pragma unroll
    for (int i = 0; i < 2; i++) {
        int idx = tid + i * 256; rB[i] = idx >> 3; cB[i] = idx & 7;
        size_t ro = ((size_t)e * H_DIM + bn0 + rB[i]) * KA_UP + cB[i] * 8;
        b1p[i] = g_w1A + ro; b2p[i] = g_w2A + ro;
    }
    uint4 pa[4], pb1[2], pb2[2];
    const uint4 Z = make_uint4(0, 0, 0, 0);

#define ULOAD(KT) do { long _o = (long)(KT) * BKW;                              \
    _Pragma("unroll") for (int i = 0; i < 4; i++)                               \
        pa[i] = aptr[i] ? *(const uint4*)(aptr[i] + _o) : Z;                    \
    _Pragma("unroll") for (int i = 0; i < 2; i++) {                             \
        pb1[i] = *(const uint4*)(b1p[i] + _o);                                  \
        pb2[i] = *(const uint4*)(b2p[i] + _o); } } while (0)

#define USTS(BUF) do {                                                          \
    _Pragma("unroll") for (int i = 0; i < 4; i++)                               \
        *(uint4*)(dsm + UA_OFF(BUF) + sw_off(rA[i], cA[i])) = pa[i];            \
    _Pragma("unroll") for (int i = 0; i < 2; i++) {                             \
        *(uint4*)(dsm + UB1_OFF(BUF) + sw_off(rB[i], cB[i])) = pb1[i];          \
        *(uint4*)(dsm + UB2_OFF(BUF) + sw_off(rB[i], cB[i])) = pb2[i]; } } while (0)

    ULOAD(0); USTS(0); __syncthreads();

    float cu[2][4][4], cv[2][4][4];
#pragma unroll
    for (int a = 0; a < 2; a++)
#pragma unroll
        for (int b = 0; b < 4; b++)
#pragma unroll
            for (int c = 0; c < 4; c++) { cu[a][b][c] = 0.0f; cv[a][b][c] = 0.0f; }

    for (int kt = 0; kt < NK_UP; kt++) {
        const int cur = kt & 1;
        if (kt + 1 < NK_UP) ULOAD(kt + 1);
        const uint32_t At = sb + UA_OFF(cur);
        const uint32_t B1t = sb + UB1_OFF(cur);
        const uint32_t B2t = sb + UB2_OFF(cur);
#pragma unroll
        for (int ks = 0; ks < 4; ks++) {
            uint32_t a[2][4];
#pragma unroll
            for (int mi = 0; mi < 2; mi++) {
                int r = wm * 32 + mi * 16 + (lane & 15);
                int c = ks * 2 + (lane >> 4);
                ldsm4(a[mi][0], a[mi][1], a[mi][2], a[mi][3], At + sw_off(r, c));
            }
#pragma unroll
            for (int bj = 0; bj < 2; bj++) {
                int r = wn * 32 + bj * 16 + ((lane >> 4) << 3) + (lane & 7);
                int c = ks * 2 + ((lane >> 3) & 1);
                int off = sw_off(r, c);
                uint32_t q0, q1, q2, q3;
                ldsm4(q0, q1, q2, q3, B1t + off);
                { uint32_t b[2] = {q0, q1};
                  mma16816(cu[0][2 * bj], a[0], b); mma16816(cu[1][2 * bj], a[1], b); }
                { uint32_t b[2] = {q2, q3};
                  mma16816(cu[0][2 * bj + 1], a[0], b); mma16816(cu[1][2 * bj + 1], a[1], b); }
                ldsm4(q0, q1, q2, q3, B2t + off);
                { uint32_t b[2] = {q0, q1};
                  mma16816(cv[0][2 * bj], a[0], b); mma16816(cv[1][2 * bj], a[1], b); }
                { uint32_t b[2] = {q2, q3};
                  mma16816(cv[0][2 * bj + 1], a[0], b); mma16816(cv[1][2 * bj + 1], a[1], b); }
            }
        }
        if (kt + 1 < NK_UP) { USTS(cur ^ 1); __syncthreads(); }
    }

    // epilogue: h = silu(u)*v -> fp16 hi/lo -> [hi,hi,lo] blocks of g_hA
#pragma unroll
    for (int mi = 0; mi < 2; mi++) {
#pragma unroll
        for (int nj = 0; nj < 4; nj++) {
            int r0 = m0 + wm * 32 + mi * 16 + (lane >> 2);
            int col = bn0 + wn * 32 + nj * 8 + (lane & 3) * 2;
#pragma unroll
            for (int half = 0; half < 2; half++) {
                int r = r0 + half * 8;
                float f0 = silu_f(cu[mi][nj][2 * half])     * cv[mi][nj][2 * half];
                float f1 = silu_f(cu[mi][nj][2 * half + 1]) * cv[mi][nj][2 * half + 1];
                __half2 hh = __floats2half2_rn(f0, f1);
                __half2 ll = __floats2half2_rn(f0 - __half2float(__low2half(hh)),
                                               f1 - __half2float(__high2half(hh)));
                __half* base = g_hA + (size_t)r * KA_DN + col;
                *(__half2*)(base)             = hh;
                *(__half2*)(base + H_DIM)     = hh;
                *(__half2*)(base + 2 * H_DIM) = ll;
            }
        }
    }
#undef ULOAD
#undef USTS
}

// ---------------- K5: down GEMM — y = h W3^T --------------------------------
// block 128M x 128N, 8 warps (2m x 4n), warp 64x32
__global__ void __launch_bounds__(256) gemm_down_mma(const int) {
    const int e = g_tile_expert[blockIdx.y];
    if (e < 0) return;
    extern __shared__ char dsm[];
    const int tid = threadIdx.x;
    const int m0 = blockIdx.y * BM;
    const int bn0 = blockIdx.x * 128;
    const uint32_t sb = smem_u32(dsm);

    const int lane = tid & 31, wid = tid >> 5;
    const int wm = wid & 1, wn = wid >> 1;

    int rA[4], cA[4];
    const __half *ap[4], *bp[4];
#pragma unroll
    for (int i = 0; i < 4; i++) {
        int idx = tid + i * 256; rA[i] = idx >> 3; cA[i] = idx & 7;
        ap[i] = g_hA + (size_t)(m0 + rA[i]) * KA_DN + cA[i] * 8;
        bp[i] = g_w3A + ((size_t)e * D_DIM + bn0 + rA[i]) * KA_DN + cA[i] * 8;
    }
    uint4 pa[4], pb[4];

#define DLOAD(KT) do { long _o = (long)(KT) * BKW;                              \
    _Pragma("unroll") for (int i = 0; i < 4; i++) {                             \
        pa[i] = *(const uint4*)(ap[i] + _o);                                    \
        pb[i] = *(const uint4*)(bp[i] + _o); } } while (0)

#define DSTS(BUF) do {                                                          \
    _Pragma("unroll") for (int i = 0; i < 4; i++) {                             \
        *(uint4*)(dsm + DA_OFF(BUF) + sw_off(rA[i], cA[i])) = pa[i];            \
        *(uint4*)(dsm + DB_OFF(BUF) + sw_off(rA[i], cA[i])) = pb[i]; } } while (0)

    DLOAD(0); DSTS(0); __syncthreads();

    float acc[4][4][4];
#pragma unroll
    for (int a = 0; a < 4; a++)
#pragma unroll
        for (int b = 0; b < 4; b++)
#pragma unroll
            for (int c = 0; c < 4; c++) acc[a][b][c] = 0.0f;

    for (int kt = 0; kt < NK_DN; kt++) {
        const int cur = kt & 1;
        if (kt + 1 < NK_DN) DLOAD(kt + 1);
        const uint32_t At = sb + DA_OFF(cur);
        const uint32_t Bt = sb + DB_OFF(cur);
#pragma unroll
        for (int ks = 0; ks < 4; ks++) {
            uint32_t a[4][4];
#pragma unroll
            for (int mi = 0; mi < 4; mi++) {
                int r = wm * 64 + mi * 16 + (lane & 15);
                int c = ks * 2 + (lane >> 4);
                ldsm4(a[mi][0], a[mi][1], a[mi][2], a[mi][3], At + sw_off(r, c));
            }
#pragma unroll
            for (int bj = 0; bj < 2; bj++) {
                int r = wn * 32 + bj * 16 + ((lane >> 4) << 3) + (lane & 7);
                int c = ks * 2 + ((lane >> 3) & 1);
                uint32_t q0, q1, q2, q3;
                ldsm4(q0, q1, q2, q3, Bt + sw_off(r, c));
                { uint32_t b[2] = {q0, q1};
#pragma unroll
                  for (int mi = 0; mi < 4; mi++) mma16816(acc[mi][2 * bj], a[mi], b); }
                { uint32_t b[2] = {q2, q3};
#pragma unroll
                  for (int mi = 0; mi < 4; mi++) mma16816(acc[mi][2 * bj + 1], a[mi], b); }
            }
        }
        if (kt + 1 < NK_DN) { DSTS(cur ^ 1); __syncthreads(); }
    }

#pragma unroll
    for (int mi = 0; mi < 4; mi++) {
#pragma unroll
        for (int nj = 0; nj < 4; nj++) {
            int r0 = m0 + wm * 64 + mi * 16 + (lane >> 2);
            int col = bn0 + wn * 32 + nj * 8 + (lane & 3) * 2;
            float2 lo = make_float2(acc[mi][nj][0], acc[mi][nj][1]);
            float2 hi = make_float2(acc[mi][nj][2], acc[mi][nj][3]);
            *(float2*)(g_y + (size_t)r0 * D_DIM + col)       = lo;
            *(float2*)(g_y + (size_t)(r0 + 8) * D_DIM + col) = hi;
        }
    }
#undef DLOAD
#undef DSTS
}

// ---------------- K6: combine ------------------------------------------------
__global__ void combine_kernel(float* __restrict__ out, int T) {
    const int nq = D_DIM / 4;
    int idx = blockIdx.x * blockDim.x + threadIdx.x;
    if (idx >= T * nq) return;
    int t = idx / nq;
    int dq = idx - t * nq;
    int r0 = g_row_of[2 * t];
    int r1 = g_row_of[2 * t + 1];
    float p0 = g_probs[2 * t];
    float p1 = g_probs[2 * t + 1];
    float4 y0 = *(const float4*)&g_y[(size_t)r0 * D_DIM + dq * 4];
    float4 y1 = *(const float4*)&g_y[(size_t)r1 * D_DIM + dq * 4];
    float4 o;
    o.x = p0 * y0.x + p1 * y1.x;
    o.y = p0 * y0.y + p1 * y1.y;
    o.z = p0 * y0.z + p1 * y1.z;
    o.w = p0 * y0.w + p1 * y1.w;
    *(float4*)&out[(size_t)t * D_DIM + dq * 4] = o;
}

// ---------------- launch -----------------------------------------------------
extern "C" void kernel_launch(void* const* d_in, const int* in_sizes, int n_in,
                              void* d_out, int out_size) {
    const float* x  = (const float*)d_in[0];
    const float* gw = (const float*)d_in[1];
    const float* w1 = (const float*)d_in[2];
    const float* w2 = (const float*)d_in[3];
    const float* w3 = (const float*)d_in[4];
    float* out = (float*)d_out;

    int T = in_sizes[0] / D_DIM;
    if (T > T_MAX) T = T_MAX;
    int m_tiles = (2 * T) / BM + E_NUM;
    if (m_tiles > MAX_TILES) m_tiles = MAX_TILES;

    cudaFuncSetAttribute(gemm_up_mma,   cudaFuncAttributeMaxDynamicSharedMemorySize, UP_SMEM);
    cudaFuncSetAttribute(gemm_down_mma, cudaFuncAttributeMaxDynamicSharedMemorySize, DN_SMEM);

    init_kernel<<<1, 32>>>();
    router_kernel<<<(T + 7) / 8, 256>>>(x, gw, T);
    scan_kernel<<<1, 32>>>(m_tiles);
    build_kernel<<<m_tiles, BM>>>();

    long xt4 = (long)T * D_DIM / 4;
    conv_x_kernel<<<(int)((xt4 + 255) / 256), 256>>>(x, xt4);
    long w12t4 = (long)E_NUM * H_DIM * D_DIM / 4;
    conv_w_kernel<<<(int)((w12t4 + 255) / 256), 256>>>(w1, 0, D_DIM, w12t4);
    conv_w_kernel<<<(int)((w12t4 + 255) / 256), 256>>>(w2, 1, D_DIM, w12t4);
    long w3t4 = (long)E_NUM * D_DIM * H_DIM / 4;
    conv_w_kernel<<<(int)((w3t4 + 255) / 256), 256>>>(w3, 2, H_DIM, w3t4);

    gemm_up_mma<<<dim3(H_DIM / 64, m_tiles), 256, UP_SMEM>>>();
    gemm_down_mma<<<dim3(D_DIM / 128, m_tiles), 256, DN_SMEM>>>(0);
    combine_kernel<<<(T * (D_DIM / 4) + 255) / 256, 256>>>(out, T);
}

// round 4
// speedup vs baseline: 4.1352x; 1.7510x over previous
#include <cuda_runtime.h>
#include <cuda_fp16.h>
#include <cstdint>

#define D_DIM 1024
#define H_DIM 2048
#define E_NUM 8
#define T_MAX 4096
#define BM 128
#define MAX_TILES 72
#define MAX_ROWS  (MAX_TILES * BM)

#define BKW 64                /* fp16 K elems per stage */
#define UP_NK 32              /* (2*D)/BKW : B is [hi|lo] K-doubled */
#define DN_NK 64              /* (2*H)/BKW */
#define STAGE_BYTES 49152     /* per-stage smem (A 16KB + B 32KB) */
#define GEMM_SMEM (3 * STAGE_BYTES + 1024)

// ---------------- device-global scratch ------------------------------------
__device__ int   g_counts[E_NUM];
__device__ int   g_offsets[E_NUM + 1];
__device__ int   g_tile_expert[MAX_TILES];
__device__ int   g_list[E_NUM * T_MAX];
__device__ float g_probs[2 * T_MAX];
__device__ int   g_gather[MAX_ROWS];
__device__ int   g_row_of[2 * T_MAX];
__device__ __half g_xH [(size_t)T_MAX * D_DIM];                 // hi only
__device__ __half g_w1A[(size_t)E_NUM * H_DIM * 2 * D_DIM];     // [hi | lo]
__device__ __half g_w2A[(size_t)E_NUM * H_DIM * 2 * D_DIM];     // [hi | lo]
__device__ __half g_w3A[(size_t)E_NUM * D_DIM * 2 * H_DIM];     // [hi | lo]
__device__ __half g_hH [(size_t)MAX_ROWS * H_DIM];              // hi only
__device__ float g_y[(size_t)MAX_ROWS * D_DIM];

// ---------------- helpers ----------------------------------------------------
__device__ __forceinline__ uint32_t smem_u32(const void* p) {
    uint32_t a;
    asm("{ .reg .u64 t; cvta.to.shared.u64 t, %1; cvt.u32.u64 %0, t; }"
        : "=r"(a) : "l"(p));
    return a;
}
__device__ __forceinline__ void ldsm4(uint32_t& r0, uint32_t& r1, uint32_t& r2,
                                      uint32_t& r3, uint32_t addr) {
    asm volatile("ldmatrix.sync.aligned.m8n8.x4.shared.b16 {%0,%1,%2,%3}, [%4];"
                 : "=r"(r0), "=r"(r1), "=r"(r2), "=r"(r3) : "r"(addr));
}
__device__ __forceinline__ void mma16816(float* c, const uint32_t* a,
                                         const uint32_t* b) {
    asm volatile(
        "mma.sync.aligned.m16n8k16.row.col.f32.f16.f16.f32 "
        "{%0,%1,%2,%3},{%4,%5,%6,%7},{%8,%9},{%0,%1,%2,%3};"
        : "+f"(c[0]), "+f"(c[1]), "+f"(c[2]), "+f"(c[3])
        : "r"(a[0]), "r"(a[1]), "r"(a[2]), "r"(a[3]), "r"(b[0]), "r"(b[1]));
}
__device__ __forceinline__ void cp16(uint32_t dst, const void* src, int srcsize) {
    asm volatile("cp.async.cg.shared.global [%0], [%1], 16, %2;"
                 :: "r"(dst), "l"(src), "r"(srcsize) : "memory");
}
#define CP_COMMIT asm volatile("cp.async.commit_group;" ::: "memory")
template <int N>
__device__ __forceinline__ void cp_wait() {
    asm volatile("cp.async.wait_group %0;" :: "n"(N) : "memory");
}
__device__ __forceinline__ float silu_f(float v) { return v / (1.0f + __expf(-v)); }
__device__ __forceinline__ int sw_off(int r, int c) {
    return r * 128 + ((c ^ (r & 7)) << 4);
}

// ---------------- K0-K3: routing (validated) --------------------------------
__global__ void init_kernel() {
    if (threadIdx.x < E_NUM) g_counts[threadIdx.x] = 0;
}

__global__ void router_kernel(const float* __restrict__ x,
                              const float* __restrict__ gw, int T) {
    int warp = blockIdx.x * (blockDim.x >> 5) + (threadIdx.x >> 5);
    int lane = threadIdx.x & 31;
    if (warp >= T) return;
    const float* xr = x + (size_t)warp * D_DIM;
    float acc[E_NUM];
#pragma unroll
    for (int e = 0; e < E_NUM; e++) acc[e] = 0.0f;
    for (int d = lane; d < D_DIM; d += 32) {
        float xv = xr[d];
#pragma unroll
        for (int e = 0; e < E_NUM; e++) acc[e] += xv * gw[e * D_DIM + d];
    }
#pragma unroll
    for (int e = 0; e < E_NUM; e++) {
#pragma unroll
        for (int off = 16; off > 0; off >>= 1)
            acc[e] += __shfl_xor_sync(0xFFFFFFFFu, acc[e], off);
    }
    if (lane == 0) {
        int e0 = 0; float s0 = acc[0];
#pragma unroll
        for (int e = 1; e < E_NUM; e++) if (acc[e] > s0) { s0 = acc[e]; e0 = e; }
        int e1 = -1; float s1 = -3.4e38f;
#pragma unroll
        for (int e = 0; e < E_NUM; e++)
            if (e != e0 && acc[e] > s1) { s1 = acc[e]; e1 = e; }
        float x1 = __expf(s1 - s0);
        float inv = 1.0f / (1.0f + x1);
        int t = warp;
        g_probs[2 * t] = inv;
        g_probs[2 * t + 1] = x1 * inv;
        int j0 = atomicAdd(&g_counts[e0], 1);
        g_list[e0 * T_MAX + j0] = (t << 1);
        int j1 = atomicAdd(&g_counts[e1], 1);
        g_list[e1 * T_MAX + j1] = (t << 1) | 1;
    }
}

__global__ void scan_kernel(int m_tiles_max) {
    if (threadIdx.x != 0 || blockIdx.x != 0) return;
    int off = 0, nt = 0;
    for (int e = 0; e < E_NUM; e++) {
        g_offsets[e] = off;
        int c = g_counts[e];
        int te = (c + BM - 1) / BM;
        for (int k = 0; k < te; k++) g_tile_expert[nt++] = e;
        off += te * BM;
    }
    g_offsets[E_NUM] = off;
    for (; nt < m_tiles_max; nt++) g_tile_expert[nt] = -1;
}

__global__ void build_kernel() {
    int tile = blockIdx.x;
    int e = g_tile_expert[tile];
    int r = tile * BM + threadIdx.x;
    if (e < 0) { g_gather[r] = -1; return; }
    int j = r - g_offsets[e];
    if (j < g_counts[e]) {
        int entry = g_list[e * T_MAX + j];
        g_gather[r] = entry >> 1;
        g_row_of[entry] = r;
    } else {
        g_gather[r] = -1;
    }
}

// ---------------- conversions ------------------------------------------------
__global__ void conv_x_kernel(const float* __restrict__ src, long total4) {
    long i = blockIdx.x * (long)blockDim.x + threadIdx.x;
    if (i >= total4) return;
    long eb = i * 4;
    float4 v = *(const float4*)(src + eb);
    __half2 h0 = __floats2half2_rn(v.x, v.y);
    __half2 h1 = __floats2half2_rn(v.z, v.w);
    *(uint2*)(g_xH + eb) = make_uint2(*(uint32_t*)&h0, *(uint32_t*)&h1);
}

__global__ void conv_w_kernel(const float* __restrict__ src, int which, int K, long total4) {
    long i = blockIdx.x * (long)blockDim.x + threadIdx.x;
    if (i >= total4) return;
    __half* dst = (which == 0) ? g_w1A : (which == 1) ? g_w2A : g_w3A;
    long eb = i * 4;
    long row = eb / K;
    int k = (int)(eb - row * K);
    float4 v = *(const float4*)(src + eb);
    __half2 h0 = __floats2half2_rn(v.x, v.y);
    __half2 h1 = __floats2half2_rn(v.z, v.w);
    __half2 l0 = __floats2half2_rn(v.x - __half2float(__low2half(h0)),
                                   v.y - __half2float(__high2half(h0)));
    __half2 l1 = __floats2half2_rn(v.z - __half2float(__low2half(h1)),
                                   v.w - __half2float(__high2half(h1)));
    __half* dr = dst + row * (size_t)(2 * K);
    *(uint2*)(dr + k)     = make_uint2(*(uint32_t*)&h0, *(uint32_t*)&h1);
    *(uint2*)(dr + K + k) = make_uint2(*(uint32_t*)&l0, *(uint32_t*)&l1);
}

// ---------------- K4: up GEMM -------------------------------------------------
// block 128M x 128N (both u and v), 8 warps (2m x 4n), warp 64x32 per matrix.
// A = x hi [T,1024], k index wraps mod 1024; B = w[hi|lo] [.,2048].
__global__ void __launch_bounds__(256, 1) gemm_up_mma() {
    const int e = g_tile_expert[blockIdx.y];
    if (e < 0) return;
    extern __shared__ char raw[];
    char* dsm = (char*)(((uintptr_t)raw + 1023) & ~(uintptr_t)1023);
    __shared__ int sg[BM];
    const int tid = threadIdx.x;
    const int m0 = blockIdx.y * BM;
    const int bn0 = blockIdx.x * 128;
    if (tid < BM) sg[tid] = g_gather[m0 + tid];
    __syncthreads();
    const uint32_t sb = smem_u32(dsm);
    const int lane = tid & 31, wid = tid >> 5;
    const int wm = wid & 1, wn = wid >> 1;

    // cp.async source assignments: A 4 chunks, B1/B2 4 chunks each
    const char* asrc[4]; int asz[4]; int dA[4];
    const char* b1s[4];
    const size_t w2delta = (const char*)g_w2A - (const char*)g_w1A;
#pragma unroll
    for (int i = 0; i < 4; i++) {
        int idx = tid + i * 256;
        int r = idx >> 3, c = idx & 7;
        dA[i] = sw_off(r, c);
        int tok = sg[r];
        asrc[i] = (tok >= 0) ? (const char*)(g_xH + (size_t)tok * D_DIM + c * 8)
                             : (const char*)g_xH;
        asz[i] = (tok >= 0) ? 16 : 0;
        b1s[i] = (const char*)(g_w1A + ((size_t)e * H_DIM + bn0 + r) * (2 * D_DIM) + c * 8);
    }

#define U_LOAD(KT) do {                                                         \
    const int _s = (KT) % 3;                                                    \
    const uint32_t _b = sb + _s * STAGE_BYTES;                                  \
    const int _ak = ((KT) & 15) * (BKW * 2);                                    \
    const long _bk = (long)(KT) * (BKW * 2);                                    \
    _Pragma("unroll") for (int i = 0; i < 4; i++) {                             \
        cp16(_b + dA[i], asrc[i] + _ak, asz[i]);                                \
        cp16(_b + 16384 + dA[i], b1s[i] + _bk, 16);                             \
        cp16(_b + 32768 + dA[i], b1s[i] + w2delta + _bk, 16);                   \
    } } while (0)

    U_LOAD(0); CP_COMMIT;
    U_LOAD(1); CP_COMMIT;

    float cu[4][4][4], cv[4][4][4];
#pragma unroll
    for (int a = 0; a < 4; a++)
#pragma unroll
        for (int b = 0; b < 4; b++)
#pragma unroll
            for (int c = 0; c < 4; c++) { cu[a][b][c] = 0.0f; cv[a][b][c] = 0.0f; }

    for (int kt = 0; kt < UP_NK; kt++) {
        cp_wait<1>(); __syncthreads();
        if (kt + 2 < UP_NK) U_LOAD(kt + 2);
        CP_COMMIT;
        const uint32_t At  = sb + (kt % 3) * STAGE_BYTES;
        const uint32_t B1t = At + 16384;
        const uint32_t B2t = At + 32768;
#pragma unroll
        for (int ks = 0; ks < 4; ks++) {
            uint32_t a[4][4];
#pragma unroll
            for (int mi = 0; mi < 4; mi++) {
                int r = wm * 64 + mi * 16 + (lane & 15);
                int c = ks * 2 + (lane >> 4);
                ldsm4(a[mi][0], a[mi][1], a[mi][2], a[mi][3], At + sw_off(r, c));
            }
#pragma unroll
            for (int bj = 0; bj < 2; bj++) {
                int r = wn * 32 + bj * 16 + ((lane >> 4) << 3) + (lane & 7);
                int c = ks * 2 + ((lane >> 3) & 1);
                int off = sw_off(r, c);
                uint32_t q0, q1, q2, q3;
                ldsm4(q0, q1, q2, q3, B1t + off);
                { uint32_t b[2] = {q0, q1};
#pragma unroll
                  for (int mi = 0; mi < 4; mi++) mma16816(cu[mi][2 * bj], a[mi], b); }
                { uint32_t b[2] = {q2, q3};
#pragma unroll
                  for (int mi = 0; mi < 4; mi++) mma16816(cu[mi][2 * bj + 1], a[mi], b); }
                ldsm4(q0, q1, q2, q3, B2t + off);
                { uint32_t b[2] = {q0, q1};
#pragma unroll
                  for (int mi = 0; mi < 4; mi++) mma16816(cv[mi][2 * bj], a[mi], b); }
                { uint32_t b[2] = {q2, q3};
#pragma unroll
                  for (int mi = 0; mi < 4; mi++) mma16816(cv[mi][2 * bj + 1], a[mi], b); }
            }
        }
    }
#undef U_LOAD

    // epilogue: h = silu(u)*v -> fp16 hi -> g_hH
#pragma unroll
    for (int mi = 0; mi < 4; mi++) {
#pragma unroll
        for (int nj = 0; nj < 4; nj++) {
            int r0 = m0 + wm * 64 + mi * 16 + (lane >> 2);
            int col = bn0 + wn * 32 + nj * 8 + (lane & 3) * 2;
#pragma unroll
            for (int h = 0; h < 2; h++) {
                int r = r0 + 8 * h;
                float f0 = silu_f(cu[mi][nj][2 * h])     * cv[mi][nj][2 * h];
                float f1 = silu_f(cu[mi][nj][2 * h + 1]) * cv[mi][nj][2 * h + 1];
                __half2 hh = __floats2half2_rn(f0, f1);
                *(__half2*)(g_hH + (size_t)r * H_DIM + col) = hh;
            }
        }
    }
}

// ---------------- K5: down GEMM ----------------------------------------------
// block 128M x 256N, 8 warps (2m x 4n), warp 64x64.
// A = h hi [rows,2048], k wraps mod 2048; B = w3 [hi|lo] [.,4096].
__global__ void __launch_bounds__(256, 1) gemm_down_mma() {
    const int e = g_tile_expert[blockIdx.y];
    if (e < 0) return;
    extern __shared__ char raw[];
    char* dsm = (char*)(((uintptr_t)raw + 1023) & ~(uintptr_t)1023);
    const int tid = threadIdx.x;
    const int m0 = blockIdx.y * BM;
    const int bn0 = blockIdx.x * 256;
    const uint32_t sb = smem_u32(dsm);
    const int lane = tid & 31, wid = tid >> 5;
    const int wm = wid & 1, wn = wid >> 1;

    const char* asrc[4]; int dA[4];
    const char* bsrc[8]; int dB[8];
#pragma unroll
    for (int i = 0; i < 4; i++) {
        int idx = tid + i * 256;
        int r = idx >> 3, c = idx & 7;
        dA[i] = sw_off(r, c);
        asrc[i] = (const char*)(g_hH + (size_t)(m0 + r) * H_DIM + c * 8);
    }
#pragma unroll
    for (int i = 0; i < 8; i++) {
        int idx = tid + i * 256;
        int r = idx >> 3, c = idx & 7;
        dB[i] = sw_off(r, c);
        bsrc[i] = (const char*)(g_w3A + ((size_t)e * D_DIM + bn0 + r) * (2 * H_DIM) + c * 8);
    }

#define D_LOAD(KT) do {                                                         \
    const int _s = (KT) % 3;                                                    \
    const uint32_t _b = sb + _s * STAGE_BYTES;                                  \
    const int _ak = ((KT) & 31) * (BKW * 2);                                    \
    const long _bk = (long)(KT) * (BKW * 2);                                    \
    _Pragma("unroll") for (int i = 0; i < 4; i++)                               \
        cp16(_b + dA[i], asrc[i] + _ak, 16);                                    \
    _Pragma("unroll") for (int i = 0; i < 8; i++)                               \
        cp16(_b + 16384 + dB[i], bsrc[i] + _bk, 16);                            \
    } while (0)

    D_LOAD(0); CP_COMMIT;
    D_LOAD(1); CP_COMMIT;

    float acc[4][8][4];
#pragma unroll
    for (int a = 0; a < 4; a++)
#pragma unroll
        for (int b = 0; b < 8; b++)
#pragma unroll
            for (int c = 0; c < 4; c++) acc[a][b][c] = 0.0f;

    for (int kt = 0; kt < DN_NK; kt++) {
        cp_wait<1>(); __syncthreads();
        if (kt + 2 < DN_NK) D_LOAD(kt + 2);
        CP_COMMIT;
        const uint32_t At = sb + (kt % 3) * STAGE_BYTES;
        const uint32_t Bt = At + 16384;
#pragma unroll
        for (int ks = 0; ks < 4; ks++) {
            uint32_t a[4][4];
#pragma unroll
            for (int mi = 0; mi < 4; mi++) {
                int r = wm * 64 + mi * 16 + (lane & 15);
                int c = ks * 2 + (lane >> 4);
                ldsm4(a[mi][0], a[mi][1], a[mi][2], a[mi][3], At + sw_off(r, c));
            }
#pragma unroll
            for (int bj = 0; bj < 4; bj++) {
                int r = wn * 64 + bj * 16 + ((lane >> 4) << 3) + (lane & 7);
                int c = ks * 2 + ((lane >> 3) & 1);
                uint32_t q0, q1, q2, q3;
                ldsm4(q0, q1, q2, q3, Bt + sw_off(r, c));
                { uint32_t b[2] = {q0, q1};
#pragma unroll
                  for (int mi = 0; mi < 4; mi++) mma16816(acc[mi][2 * bj], a[mi], b); }
                { uint32_t b[2] = {q2, q3};
#pragma unroll
                  for (int mi = 0; mi < 4; mi++) mma16816(acc[mi][2 * bj + 1], a[mi], b); }
            }
        }
    }
#undef D_LOAD

#pragma unroll
    for (int mi = 0; mi < 4; mi++) {
#pragma unroll
        for (int nj = 0; nj < 8; nj++) {
            int r0 = m0 + wm * 64 + mi * 16 + (lane >> 2);
            int col = bn0 + wn * 64 + nj * 8 + (lane & 3) * 2;
            float2 lo = make_float2(acc[mi][nj][0], acc[mi][nj][1]);
            float2 hi = make_float2(acc[mi][nj][2], acc[mi][nj][3]);
            *(float2*)(g_y + (size_t)r0 * D_DIM + col)       = lo;
            *(float2*)(g_y + (size_t)(r0 + 8) * D_DIM + col) = hi;
        }
    }
}

// ---------------- K6: combine -------------------------------------------------
__global__ void combine_kernel(float* __restrict__ out, int T) {
    const int nq = D_DIM / 4;
    int idx = blockIdx.x * blockDim.x + threadIdx.x;
    if (idx >= T * nq) return;
    int t = idx / nq;
    int dq = idx - t * nq;
    int r0 = g_row_of[2 * t];
    int r1 = g_row_of[2 * t + 1];
    float p0 = g_probs[2 * t];
    float p1 = g_probs[2 * t + 1];
    float4 y0 = *(const float4*)&g_y[(size_t)r0 * D_DIM + dq * 4];
    float4 y1 = *(const float4*)&g_y[(size_t)r1 * D_DIM + dq * 4];
    float4 o;
    o.x = p0 * y0.x + p1 * y1.x;
    o.y = p0 * y0.y + p1 * y1.y;
    o.z = p0 * y0.z + p1 * y1.z;
    o.w = p0 * y0.w + p1 * y1.w;
    *(float4*)&out[(size_t)t * D_DIM + dq * 4] = o;
}

// ---------------- launch -------------------------------------------------------
extern "C" void kernel_launch(void* const* d_in, const int* in_sizes, int n_in,
                              void* d_out, int out_size) {
    const float* x  = (const float*)d_in[0];
    const float* gw = (const float*)d_in[1];
    const float* w1 = (const float*)d_in[2];
    const float* w2 = (const float*)d_in[3];
    const float* w3 = (const float*)d_in[4];
    float* out = (float*)d_out;

    int T = in_sizes[0] / D_DIM;
    if (T > T_MAX) T = T_MAX;
    int m_tiles = (2 * T) / BM + E_NUM;
    if (m_tiles > MAX_TILES) m_tiles = MAX_TILES;

    cudaFuncSetAttribute(gemm_up_mma,   cudaFuncAttributeMaxDynamicSharedMemorySize, GEMM_SMEM);
    cudaFuncSetAttribute(gemm_down_mma, cudaFuncAttributeMaxDynamicSharedMemorySize, GEMM_SMEM);

    init_kernel<<<1, 32>>>();
    router_kernel<<<(T + 7) / 8, 256>>>(x, gw, T);
    scan_kernel<<<1, 32>>>(m_tiles);
    build_kernel<<<m_tiles, BM>>>();

    long xt4 = (long)T * D_DIM / 4;
    conv_x_kernel<<<(int)((xt4 + 255) / 256), 256>>>(x, xt4);
    long w12t4 = (long)E_NUM * H_DIM * D_DIM / 4;
    conv_w_kernel<<<(int)((w12t4 + 255) / 256), 256>>>(w1, 0, D_DIM, w12t4);
    conv_w_kernel<<<(int)((w12t4 + 255) / 256), 256>>>(w2, 1, D_DIM, w12t4);
    long w3t4 = (long)E_NUM * D_DIM * H_DIM / 4;
    conv_w_kernel<<<(int)((w3t4 + 255) / 256), 256>>>(w3, 2, H_DIM, w3t4);

    gemm_up_mma<<<dim3(H_DIM / 128, m_tiles), 256, GEMM_SMEM>>>();
    gemm_down_mma<<<dim3(D_DIM / 256, m_tiles), 256, GEMM_SMEM>>>();
    combine_kernel<<<(T * (D_DIM / 4) + 255) / 256, 256>>>(out, T);
}

// round 5
// speedup vs baseline: 5.5979x; 1.3537x over previous
#include <cuda_runtime.h>
#include <cuda_fp16.h>
#include <cstdint>

#define D_DIM 1024
#define H_DIM 2048
#define E_NUM 8
#define T_MAX 4096
#define BM 128
#define MAX_TILES 72
#define MAX_ROWS  (MAX_TILES * BM)

#define BKW 64                /* fp16 K elems per stage */
#define UP_NK 16              /* D/BKW : single-term fp16 */
#define DN_NK 64              /* (2*H)/BKW : w3 stays [hi|lo] */
#define STAGE_BYTES 49152     /* per-stage smem (A 16KB + B 32KB) */
#define GEMM_SMEM (3 * STAGE_BYTES + 1024)

// ---------------- device-global scratch ------------------------------------
__device__ int   g_counts[E_NUM];
__device__ int   g_offsets[E_NUM + 1];
__device__ int   g_tile_expert[MAX_TILES];
__device__ int   g_list[E_NUM * T_MAX];
__device__ float g_probs[2 * T_MAX];
__device__ int   g_gather[MAX_ROWS];
__device__ int   g_row_of[2 * T_MAX];
__device__ __half g_xH [(size_t)T_MAX * D_DIM];                 // hi only
__device__ __half g_w1H[(size_t)E_NUM * H_DIM * D_DIM];         // hi only
__device__ __half g_w2H[(size_t)E_NUM * H_DIM * D_DIM];         // hi only
__device__ __half g_w3A[(size_t)E_NUM * D_DIM * 2 * H_DIM];     // [hi | lo]
__device__ __half g_hH [(size_t)MAX_ROWS * H_DIM];              // hi only
__device__ float g_y[(size_t)MAX_ROWS * D_DIM];

// ---------------- helpers ----------------------------------------------------
__device__ __forceinline__ uint32_t smem_u32(const void* p) {
    uint32_t a;
    asm("{ .reg .u64 t; cvta.to.shared.u64 t, %1; cvt.u32.u64 %0, t; }"
        : "=r"(a) : "l"(p));
    return a;
}
__device__ __forceinline__ void ldsm4(uint32_t& r0, uint32_t& r1, uint32_t& r2,
                                      uint32_t& r3, uint32_t addr) {
    asm volatile("ldmatrix.sync.aligned.m8n8.x4.shared.b16 {%0,%1,%2,%3}, [%4];"
                 : "=r"(r0), "=r"(r1), "=r"(r2), "=r"(r3) : "r"(addr));
}
__device__ __forceinline__ void mma16816(float* c, const uint32_t* a,
                                         const uint32_t* b) {
    asm volatile(
        "mma.sync.aligned.m16n8k16.row.col.f32.f16.f16.f32 "
        "{%0,%1,%2,%3},{%4,%5,%6,%7},{%8,%9},{%0,%1,%2,%3};"
        : "+f"(c[0]), "+f"(c[1]), "+f"(c[2]), "+f"(c[3])
        : "r"(a[0]), "r"(a[1]), "r"(a[2]), "r"(a[3]), "r"(b[0]), "r"(b[1]));
}
__device__ __forceinline__ void cp16(uint32_t dst, const void* src, int srcsize) {
    asm volatile("cp.async.cg.shared.global [%0], [%1], 16, %2;"
                 :: "r"(dst), "l"(src), "r"(srcsize) : "memory");
}
#define CP_COMMIT asm volatile("cp.async.commit_group;" ::: "memory")
template <int N>
__device__ __forceinline__ void cp_wait() {
    asm volatile("cp.async.wait_group %0;" :: "n"(N) : "memory");
}
__device__ __forceinline__ float silu_f(float v) { return v / (1.0f + __expf(-v)); }
__device__ __forceinline__ int sw_off(int r, int c) {
    return r * 128 + ((c ^ (r & 7)) << 4);
}

// ---------------- K0-K3: routing (validated) --------------------------------
__global__ void init_kernel() {
    if (threadIdx.x < E_NUM) g_counts[threadIdx.x] = 0;
}

__global__ void router_kernel(const float* __restrict__ x,
                              const float* __restrict__ gw, int T) {
    int warp = blockIdx.x * (blockDim.x >> 5) + (threadIdx.x >> 5);
    int lane = threadIdx.x & 31;
    if (warp >= T) return;
    const float* xr = x + (size_t)warp * D_DIM;
    float acc[E_NUM];
#pragma unroll
    for (int e = 0; e < E_NUM; e++) acc[e] = 0.0f;
    for (int d = lane; d < D_DIM; d += 32) {
        float xv = xr[d];
#pragma unroll
        for (int e = 0; e < E_NUM; e++) acc[e] += xv * gw[e * D_DIM + d];
    }
#pragma unroll
    for (int e = 0; e < E_NUM; e++) {
#pragma unroll
        for (int off = 16; off > 0; off >>= 1)
            acc[e] += __shfl_xor_sync(0xFFFFFFFFu, acc[e], off);
    }
    if (lane == 0) {
        int e0 = 0; float s0 = acc[0];
#pragma unroll
        for (int e = 1; e < E_NUM; e++) if (acc[e] > s0) { s0 = acc[e]; e0 = e; }
        int e1 = -1; float s1 = -3.4e38f;
#pragma unroll
        for (int e = 0; e < E_NUM; e++)
            if (e != e0 && acc[e] > s1) { s1 = acc[e]; e1 = e; }
        float x1 = __expf(s1 - s0);
        float inv = 1.0f / (1.0f + x1);
        int t = warp;
        g_probs[2 * t] = inv;
        g_probs[2 * t + 1] = x1 * inv;
        int j0 = atomicAdd(&g_counts[e0], 1);
        g_list[e0 * T_MAX + j0] = (t << 1);
        int j1 = atomicAdd(&g_counts[e1], 1);
        g_list[e1 * T_MAX + j1] = (t << 1) | 1;
    }
}

__global__ void scan_kernel(int m_tiles_max) {
    if (threadIdx.x != 0 || blockIdx.x != 0) return;
    int off = 0, nt = 0;
    for (int e = 0; e < E_NUM; e++) {
        g_offsets[e] = off;
        int c = g_counts[e];
        int te = (c + BM - 1) / BM;
        for (int k = 0; k < te; k++) g_tile_expert[nt++] = e;
        off += te * BM;
    }
    g_offsets[E_NUM] = off;
    for (; nt < m_tiles_max; nt++) g_tile_expert[nt] = -1;
}

__global__ void build_kernel() {
    int tile = blockIdx.x;
    int e = g_tile_expert[tile];
    int r = tile * BM + threadIdx.x;
    if (e < 0) { g_gather[r] = -1; return; }
    int j = r - g_offsets[e];
    if (j < g_counts[e]) {
        int entry = g_list[e * T_MAX + j];
        g_gather[r] = entry >> 1;
        g_row_of[entry] = r;
    } else {
        g_gather[r] = -1;
    }
}

// ---------------- conversions ------------------------------------------------
__global__ void conv_x_kernel(const float* __restrict__ src, long total4) {
    long i = blockIdx.x * (long)blockDim.x + threadIdx.x;
    if (i >= total4) return;
    long eb = i * 4;
    float4 v = *(const float4*)(src + eb);
    __half2 h0 = __floats2half2_rn(v.x, v.y);
    __half2 h1 = __floats2half2_rn(v.z, v.w);
    *(uint2*)(g_xH + eb) = make_uint2(*(uint32_t*)&h0, *(uint32_t*)&h1);
}

// hi-only weight conversion (w1, w2)
__global__ void conv_w_hi_kernel(const float* __restrict__ src, int which, long total4) {
    long i = blockIdx.x * (long)blockDim.x + threadIdx.x;
    if (i >= total4) return;
    __half* dst = (which == 0) ? g_w1H : g_w2H;
    long eb = i * 4;
    float4 v = *(const float4*)(src + eb);
    __half2 h0 = __floats2half2_rn(v.x, v.y);
    __half2 h1 = __floats2half2_rn(v.z, v.w);
    *(uint2*)(dst + eb) = make_uint2(*(uint32_t*)&h0, *(uint32_t*)&h1);
}

// [hi|lo] conversion (w3 only)
__global__ void conv_w3_kernel(const float* __restrict__ src, long total4) {
    long i = blockIdx.x * (long)blockDim.x + threadIdx.x;
    if (i >= total4) return;
    const int K = H_DIM;
    long eb = i * 4;
    long row = eb / K;
    int k = (int)(eb - row * K);
    float4 v = *(const float4*)(src + eb);
    __half2 h0 = __floats2half2_rn(v.x, v.y);
    __half2 h1 = __floats2half2_rn(v.z, v.w);
    __half2 l0 = __floats2half2_rn(v.x - __half2float(__low2half(h0)),
                                   v.y - __half2float(__high2half(h0)));
    __half2 l1 = __floats2half2_rn(v.z - __half2float(__low2half(h1)),
                                   v.w - __half2float(__high2half(h1)));
    __half* dr = g_w3A + row * (size_t)(2 * K);
    *(uint2*)(dr + k)     = make_uint2(*(uint32_t*)&h0, *(uint32_t*)&h1);
    *(uint2*)(dr + K + k) = make_uint2(*(uint32_t*)&l0, *(uint32_t*)&l1);
}

// ---------------- K4: up GEMM -------------------------------------------------
// block 128M x 128N (both u and v), 8 warps (2m x 4n), warp 64x32 per matrix.
// A = x hi [T,1024]; B1 = w1 hi [.,1024]; B2 = w2 hi [.,1024]. K=1024, 16 iters.
__global__ void __launch_bounds__(256, 1) gemm_up_mma() {
    const int e = g_tile_expert[blockIdx.y];
    if (e < 0) return;
    extern __shared__ char raw[];
    char* dsm = (char*)(((uintptr_t)raw + 1023) & ~(uintptr_t)1023);
    __shared__ int sg[BM];
    const int tid = threadIdx.x;
    const int m0 = blockIdx.y * BM;
    const int bn0 = blockIdx.x * 128;
    if (tid < BM) sg[tid] = g_gather[m0 + tid];
    __syncthreads();
    const uint32_t sb = smem_u32(dsm);
    const int lane = tid & 31, wid = tid >> 5;
    const int wm = wid & 1, wn = wid >> 1;

    const char* asrc[4]; int asz[4]; int dA[4];
    const char* b1s[4];
    const size_t w2delta = (const char*)g_w2H - (const char*)g_w1H;
#pragma unroll
    for (int i = 0; i < 4; i++) {
        int idx = tid + i * 256;
        int r = idx >> 3, c = idx & 7;
        dA[i] = sw_off(r, c);
        int tok = sg[r];
        asrc[i] = (tok >= 0) ? (const char*)(g_xH + (size_t)tok * D_DIM + c * 8)
                             : (const char*)g_xH;
        asz[i] = (tok >= 0) ? 16 : 0;
        b1s[i] = (const char*)(g_w1H + ((size_t)e * H_DIM + bn0 + r) * D_DIM + c * 8);
    }

#define U_LOAD(KT) do {                                                         \
    const int _s = (KT) % 3;                                                    \
    const uint32_t _b = sb + _s * STAGE_BYTES;                                  \
    const int _k = (KT) * (BKW * 2);                                            \
    _Pragma("unroll") for (int i = 0; i < 4; i++) {                             \
        cp16(_b + dA[i], asrc[i] + _k, asz[i]);                                 \
        cp16(_b + 16384 + dA[i], b1s[i] + _k, 16);                              \
        cp16(_b + 32768 + dA[i], b1s[i] + w2delta + _k, 16);                    \
    } } while (0)

    U_LOAD(0); CP_COMMIT;
    U_LOAD(1); CP_COMMIT;

    float cu[4][4][4], cv[4][4][4];
#pragma unroll
    for (int a = 0; a < 4; a++)
#pragma unroll
        for (int b = 0; b < 4; b++)
#pragma unroll
            for (int c = 0; c < 4; c++) { cu[a][b][c] = 0.0f; cv[a][b][c] = 0.0f; }

    for (int kt = 0; kt < UP_NK; kt++) {
        cp_wait<1>(); __syncthreads();
        if (kt + 2 < UP_NK) U_LOAD(kt + 2);
        CP_COMMIT;
        const uint32_t At  = sb + (kt % 3) * STAGE_BYTES;
        const uint32_t B1t = At + 16384;
        const uint32_t B2t = At + 32768;
#pragma unroll
        for (int ks = 0; ks < 4; ks++) {
            uint32_t a[4][4];
#pragma unroll
            for (int mi = 0; mi < 4; mi++) {
                int r = wm * 64 + mi * 16 + (lane & 15);
                int c = ks * 2 + (lane >> 4);
                ldsm4(a[mi][0], a[mi][1], a[mi][2], a[mi][3], At + sw_off(r, c));
            }
#pragma unroll
            for (int bj = 0; bj < 2; bj++) {
                int r = wn * 32 + bj * 16 + ((lane >> 4) << 3) + (lane & 7);
                int c = ks * 2 + ((lane >> 3) & 1);
                int off = sw_off(r, c);
                uint32_t q0, q1, q2, q3;
                ldsm4(q0, q1, q2, q3, B1t + off);
                { uint32_t b[2] = {q0, q1};
#pragma unroll
                  for (int mi = 0; mi < 4; mi++) mma16816(cu[mi][2 * bj], a[mi], b); }
                { uint32_t b[2] = {q2, q3};
#pragma unroll
                  for (int mi = 0; mi < 4; mi++) mma16816(cu[mi][2 * bj + 1], a[mi], b); }
                ldsm4(q0, q1, q2, q3, B2t + off);
                { uint32_t b[2] = {q0, q1};
#pragma unroll
                  for (int mi = 0; mi < 4; mi++) mma16816(cv[mi][2 * bj], a[mi], b); }
                { uint32_t b[2] = {q2, q3};
#pragma unroll
                  for (int mi = 0; mi < 4; mi++) mma16816(cv[mi][2 * bj + 1], a[mi], b); }
            }
        }
    }
#undef U_LOAD

    // epilogue: h = silu(u)*v -> fp16 hi -> g_hH
#pragma unroll
    for (int mi = 0; mi < 4; mi++) {
#pragma unroll
        for (int nj = 0; nj < 4; nj++) {
            int r0 = m0 + wm * 64 + mi * 16 + (lane >> 2);
            int col = bn0 + wn * 32 + nj * 8 + (lane & 3) * 2;
#pragma unroll
            for (int h = 0; h < 2; h++) {
                int r = r0 + 8 * h;
                float f0 = silu_f(cu[mi][nj][2 * h])     * cv[mi][nj][2 * h];
                float f1 = silu_f(cu[mi][nj][2 * h + 1]) * cv[mi][nj][2 * h + 1];
                __half2 hh = __floats2half2_rn(f0, f1);
                *(__half2*)(g_hH + (size_t)r * H_DIM + col) = hh;
            }
        }
    }
}

// ---------------- K5: down GEMM ----------------------------------------------
// block 128M x 256N, 8 warps (2m x 4n), warp 64x64.
// A = h hi [rows,2048], k wraps mod 2048; B = w3 [hi|lo] [.,4096].
__global__ void __launch_bounds__(256, 1) gemm_down_mma() {
    const int e = g_tile_expert[blockIdx.y];
    if (e < 0) return;
    extern __shared__ char raw[];
    char* dsm = (char*)(((uintptr_t)raw + 1023) & ~(uintptr_t)1023);
    const int tid = threadIdx.x;
    const int m0 = blockIdx.y * BM;
    const int bn0 = blockIdx.x * 256;
    const uint32_t sb = smem_u32(dsm);
    const int lane = tid & 31, wid = tid >> 5;
    const int wm = wid & 1, wn = wid >> 1;

    const char* asrc[4]; int dA[4];
    const char* bsrc[8]; int dB[8];
#pragma unroll
    for (int i = 0; i < 4; i++) {
        int idx = tid + i * 256;
        int r = idx >> 3, c = idx & 7;
        dA[i] = sw_off(r, c);
        asrc[i] = (const char*)(g_hH + (size_t)(m0 + r) * H_DIM + c * 8);
    }
#pragma unroll
    for (int i = 0; i < 8; i++) {
        int idx = tid + i * 256;
        int r = idx >> 3, c = idx & 7;
        dB[i] = sw_off(r, c);
        bsrc[i] = (const char*)(g_w3A + ((size_t)e * D_DIM + bn0 + r) * (2 * H_DIM) + c * 8);
    }

#define D_LOAD(KT) do {                                                         \
    const int _s = (KT) % 3;                                                    \
    const uint32_t _b = sb + _s * STAGE_BYTES;                                  \
    const int _ak = ((KT) & 31) * (BKW * 2);                                    \
    const long _bk = (long)(KT) * (BKW * 2);                                    \
    _Pragma("unroll") for (int i = 0; i < 4; i++)                               \
        cp16(_b + dA[i], asrc[i] + _ak, 16);                                    \
    _Pragma("unroll") for (int i = 0; i < 8; i++)                               \
        cp16(_b + 16384 + dB[i], bsrc[i] + _bk, 16);                            \
    } while (0)

    D_LOAD(0); CP_COMMIT;
    D_LOAD(1); CP_COMMIT;

    float acc[4][8][4];
#pragma unroll
    for (int a = 0; a < 4; a++)
#pragma unroll
        for (int b = 0; b < 8; b++)
#pragma unroll
            for (int c = 0; c < 4; c++) acc[a][b][c] = 0.0f;

    for (int kt = 0; kt < DN_NK; kt++) {
        cp_wait<1>(); __syncthreads();
        if (kt + 2 < DN_NK) D_LOAD(kt + 2);
        CP_COMMIT;
        const uint32_t At = sb + (kt % 3) * STAGE_BYTES;
        const uint32_t Bt = At + 16384;
#pragma unroll
        for (int ks = 0; ks < 4; ks++) {
            uint32_t a[4][4];
#pragma unroll
            for (int mi = 0; mi < 4; mi++) {
                int r = wm * 64 + mi * 16 + (lane & 15);
                int c = ks * 2 + (lane >> 4);
                ldsm4(a[mi][0], a[mi][1], a[mi][2], a[mi][3], At + sw_off(r, c));
            }
#pragma unroll
            for (int bj = 0; bj < 4; bj++) {
                int r = wn * 64 + bj * 16 + ((lane >> 4) << 3) + (lane & 7);
                int c = ks * 2 + ((lane >> 3) & 1);
                uint32_t q0, q1, q2, q3;
                ldsm4(q0, q1, q2, q3, Bt + sw_off(r, c));
                { uint32_t b[2] = {q0, q1};
#pragma unroll
                  for (int mi = 0; mi < 4; mi++) mma16816(acc[mi][2 * bj], a[mi], b); }
                { uint32_t b[2] = {q2, q3};
#pragma unroll
                  for (int mi = 0; mi < 4; mi++) mma16816(acc[mi][2 * bj + 1], a[mi], b); }
            }
        }
    }
#undef D_LOAD

#pragma unroll
    for (int mi = 0; mi < 4; mi++) {
#pragma unroll
        for (int nj = 0; nj < 8; nj++) {
            int r0 = m0 + wm * 64 + mi * 16 + (lane >> 2);
            int col = bn0 + wn * 64 + nj * 8 + (lane & 3) * 2;
            float2 lo = make_float2(acc[mi][nj][0], acc[mi][nj][1]);
            float2 hi = make_float2(acc[mi][nj][2], acc[mi][nj][3]);
            *(float2*)(g_y + (size_t)r0 * D_DIM + col)       = lo;
            *(float2*)(g_y + (size_t)(r0 + 8) * D_DIM + col) = hi;
        }
    }
}

// ---------------- K6: combine -------------------------------------------------
__global__ void combine_kernel(float* __restrict__ out, int T) {
    const int nq = D_DIM / 4;
    int idx = blockIdx.x * blockDim.x + threadIdx.x;
    if (idx >= T * nq) return;
    int t = idx / nq;
    int dq = idx - t * nq;
    int r0 = g_row_of[2 * t];
    int r1 = g_row_of[2 * t + 1];
    float p0 = g_probs[2 * t];
    float p1 = g_probs[2 * t + 1];
    float4 y0 = *(const float4*)&g_y[(size_t)r0 * D_DIM + dq * 4];
    float4 y1 = *(const float4*)&g_y[(size_t)r1 * D_DIM + dq * 4];
    float4 o;
    o.x = p0 * y0.x + p1 * y1.x;
    o.y = p0 * y0.y + p1 * y1.y;
    o.z = p0 * y0.z + p1 * y1.z;
    o.w = p0 * y0.w + p1 * y1.w;
    *(float4*)&out[(size_t)t * D_DIM + dq * 4] = o;
}

// ---------------- launch -------------------------------------------------------
extern "C" void kernel_launch(void* const* d_in, const int* in_sizes, int n_in,
                              void* d_out, int out_size) {
    const float* x  = (const float*)d_in[0];
    const float* gw = (const float*)d_in[1];
    const float* w1 = (const float*)d_in[2];
    const float* w2 = (const float*)d_in[3];
    const float* w3 = (const float*)d_in[4];
    float* out = (float*)d_out;

    int T = in_sizes[0] / D_DIM;
    if (T > T_MAX) T = T_MAX;
    int m_tiles = (2 * T) / BM + E_NUM;
    if (m_tiles > MAX_TILES) m_tiles = MAX_TILES;

    cudaFuncSetAttribute(gemm_up_mma,   cudaFuncAttributeMaxDynamicSharedMemorySize, GEMM_SMEM);
    cudaFuncSetAttribute(gemm_down_mma, cudaFuncAttributeMaxDynamicSharedMemorySize, GEMM_SMEM);

    init_kernel<<<1, 32>>>();
    router_kernel<<<(T + 7) / 8, 256>>>(x, gw, T);
    scan_kernel<<<1, 32>>>(m_tiles);
    build_kernel<<<m_tiles, BM>>>();

    long xt4 = (long)T * D_DIM / 4;
    conv_x_kernel<<<(int)((xt4 + 255) / 256), 256>>>(x, xt4);
    long w12t4 = (long)E_NUM * H_DIM * D_DIM / 4;
    conv_w_hi_kernel<<<(int)((w12t4 + 255) / 256), 256>>>(w1, 0, w12t4);
    conv_w_hi_kernel<<<(int)((w12t4 + 255) / 256), 256>>>(w2, 1, w12t4);
    long w3t4 = (long)E_NUM * D_DIM * H_DIM / 4;
    conv_w3_kernel<<<(int)((w3t4 + 255) / 256), 256>>>(w3, w3t4);

    gemm_up_mma<<<dim3(H_DIM / 128, m_tiles), 256, GEMM_SMEM>>>();
    gemm_down_mma<<<dim3(D_DIM / 256, m_tiles), 256, GEMM_SMEM>>>();
    combine_kernel<<<(T * (D_DIM / 4) + 255) / 256, 256>>>(out, T);
}

// round 6
// speedup vs baseline: 6.8073x; 1.2161x over previous
#include <cuda_runtime.h>
#include <cuda_fp16.h>
#include <cstdint>

#define D_DIM 1024
#define H_DIM 2048
#define E_NUM 8
#define T_MAX 4096
#define BM 128
#define MAX_TILES 72
#define MAX_ROWS  (MAX_TILES * BM)

#define BKW 64                /* fp16 K elems per stage */
#define UP_NK 16              /* D/BKW */
#define DN_NK 32              /* H/BKW : w3 hi-only now */
#define STAGE_BYTES 49152     /* per-stage smem (A 16KB + B 32KB) */
#define GEMM_SMEM (3 * STAGE_BYTES + 1024)

// ---------------- device-global scratch ------------------------------------
__device__ int   g_counts[E_NUM];
__device__ int   g_offsets[E_NUM + 1];
__device__ int   g_tile_expert[MAX_TILES];
__device__ int   g_list[E_NUM * T_MAX];
__device__ float g_probs[2 * T_MAX];
__device__ int   g_gather[MAX_ROWS];
__device__ int   g_row_of[2 * T_MAX];
__device__ __half g_xH [(size_t)T_MAX * D_DIM];                 // hi only
__device__ __half g_w1H[(size_t)E_NUM * H_DIM * D_DIM];         // hi only
__device__ __half g_w2H[(size_t)E_NUM * H_DIM * D_DIM];         // hi only
__device__ __half g_w3H[(size_t)E_NUM * D_DIM * H_DIM];         // hi only
__device__ __half g_hH [(size_t)MAX_ROWS * H_DIM];              // hi only
__device__ float g_y[(size_t)MAX_ROWS * D_DIM];

// ---------------- helpers ----------------------------------------------------
__device__ __forceinline__ uint32_t smem_u32(const void* p) {
    uint32_t a;
    asm("{ .reg .u64 t; cvta.to.shared.u64 t, %1; cvt.u32.u64 %0, t; }"
        : "=r"(a) : "l"(p));
    return a;
}
__device__ __forceinline__ void ldsm4(uint32_t& r0, uint32_t& r1, uint32_t& r2,
                                      uint32_t& r3, uint32_t addr) {
    asm volatile("ldmatrix.sync.aligned.m8n8.x4.shared.b16 {%0,%1,%2,%3}, [%4];"
                 : "=r"(r0), "=r"(r1), "=r"(r2), "=r"(r3) : "r"(addr));
}
__device__ __forceinline__ void mma16816(float* c, const uint32_t* a,
                                         const uint32_t* b) {
    asm volatile(
        "mma.sync.aligned.m16n8k16.row.col.f32.f16.f16.f32 "
        "{%0,%1,%2,%3},{%4,%5,%6,%7},{%8,%9},{%0,%1,%2,%3};"
        : "+f"(c[0]), "+f"(c[1]), "+f"(c[2]), "+f"(c[3])
        : "r"(a[0]), "r"(a[1]), "r"(a[2]), "r"(a[3]), "r"(b[0]), "r"(b[1]));
}
__device__ __forceinline__ void cp16(uint32_t dst, const void* src, int srcsize) {
    asm volatile("cp.async.cg.shared.global [%0], [%1], 16, %2;"
                 :: "r"(dst), "l"(src), "r"(srcsize) : "memory");
}
#define CP_COMMIT asm volatile("cp.async.commit_group;" ::: "memory")
template <int N>
__device__ __forceinline__ void cp_wait() {
    asm volatile("cp.async.wait_group %0;" :: "n"(N) : "memory");
}
__device__ __forceinline__ float silu_f(float v) { return v / (1.0f + __expf(-v)); }
__device__ __forceinline__ int sw_off(int r, int c) {
    return r * 128 + ((c ^ (r & 7)) << 4);
}

// ---------------- K0-K3: routing (validated) --------------------------------
__global__ void init_kernel() {
    if (threadIdx.x < E_NUM) g_counts[threadIdx.x] = 0;
}

__global__ void router_kernel(const float* __restrict__ x,
                              const float* __restrict__ gw, int T) {
    int warp = blockIdx.x * (blockDim.x >> 5) + (threadIdx.x >> 5);
    int lane = threadIdx.x & 31;
    if (warp >= T) return;
    const float* xr = x + (size_t)warp * D_DIM;
    float acc[E_NUM];
#pragma unroll
    for (int e = 0; e < E_NUM; e++) acc[e] = 0.0f;
    for (int d = lane; d < D_DIM; d += 32) {
        float xv = xr[d];
#pragma unroll
        for (int e = 0; e < E_NUM; e++) acc[e] += xv * gw[e * D_DIM + d];
    }
#pragma unroll
    for (int e = 0; e < E_NUM; e++) {
#pragma unroll
        for (int off = 16; off > 0; off >>= 1)
            acc[e] += __shfl_xor_sync(0xFFFFFFFFu, acc[e], off);
    }
    if (lane == 0) {
        int e0 = 0; float s0 = acc[0];
#pragma unroll
        for (int e = 1; e < E_NUM; e++) if (acc[e] > s0) { s0 = acc[e]; e0 = e; }
        int e1 = -1; float s1 = -3.4e38f;
#pragma unroll
        for (int e = 0; e < E_NUM; e++)
            if (e != e0 && acc[e] > s1) { s1 = acc[e]; e1 = e; }
        float x1 = __expf(s1 - s0);
        float inv = 1.0f / (1.0f + x1);
        int t = warp;
        g_probs[2 * t] = inv;
        g_probs[2 * t + 1] = x1 * inv;
        int j0 = atomicAdd(&g_counts[e0], 1);
        g_list[e0 * T_MAX + j0] = (t << 1);
        int j1 = atomicAdd(&g_counts[e1], 1);
        g_list[e1 * T_MAX + j1] = (t << 1) | 1;
    }
}

__global__ void scan_kernel(int m_tiles_max) {
    if (threadIdx.x != 0 || blockIdx.x != 0) return;
    int off = 0, nt = 0;
    for (int e = 0; e < E_NUM; e++) {
        g_offsets[e] = off;
        int c = g_counts[e];
        int te = (c + BM - 1) / BM;
        for (int k = 0; k < te; k++) g_tile_expert[nt++] = e;
        off += te * BM;
    }
    g_offsets[E_NUM] = off;
    for (; nt < m_tiles_max; nt++) g_tile_expert[nt] = -1;
}

__global__ void build_kernel() {
    int tile = blockIdx.x;
    int e = g_tile_expert[tile];
    int r = tile * BM + threadIdx.x;
    if (e < 0) { g_gather[r] = -1; return; }
    int j = r - g_offsets[e];
    if (j < g_counts[e]) {
        int entry = g_list[e * T_MAX + j];
        g_gather[r] = entry >> 1;
        g_row_of[entry] = r;
    } else {
        g_gather[r] = -1;
    }
}

// ---------------- conversions ------------------------------------------------
__global__ void conv_x_kernel(const float* __restrict__ src, long total4) {
    long i = blockIdx.x * (long)blockDim.x + threadIdx.x;
    if (i >= total4) return;
    long eb = i * 4;
    float4 v = *(const float4*)(src + eb);
    __half2 h0 = __floats2half2_rn(v.x, v.y);
    __half2 h1 = __floats2half2_rn(v.z, v.w);
    *(uint2*)(g_xH + eb) = make_uint2(*(uint32_t*)&h0, *(uint32_t*)&h1);
}

// hi-only weight conversion (w1, w2, w3)
__global__ void conv_w_hi_kernel(const float* __restrict__ src, int which, long total4) {
    long i = blockIdx.x * (long)blockDim.x + threadIdx.x;
    if (i >= total4) return;
    __half* dst = (which == 0) ? g_w1H : (which == 1) ? g_w2H : g_w3H;
    long eb = i * 4;
    float4 v = *(const float4*)(src + eb);
    __half2 h0 = __floats2half2_rn(v.x, v.y);
    __half2 h1 = __floats2half2_rn(v.z, v.w);
    *(uint2*)(dst + eb) = make_uint2(*(uint32_t*)&h0, *(uint32_t*)&h1);
}

// ---------------- K4: up GEMM -------------------------------------------------
// block 128M x 128N (both u and v), 8 warps (2m x 4n), warp 64x32 per matrix.
__global__ void __launch_bounds__(256, 1) gemm_up_mma() {
    const int e = g_tile_expert[blockIdx.y];
    if (e < 0) return;
    extern __shared__ char raw[];
    char* dsm = (char*)(((uintptr_t)raw + 1023) & ~(uintptr_t)1023);
    __shared__ int sg[BM];
    const int tid = threadIdx.x;
    const int m0 = blockIdx.y * BM;
    const int bn0 = blockIdx.x * 128;
    if (tid < BM) sg[tid] = g_gather[m0 + tid];
    __syncthreads();
    const uint32_t sb = smem_u32(dsm);
    const int lane = tid & 31, wid = tid >> 5;
    const int wm = wid & 1, wn = wid >> 1;

    const char* asrc[4]; int asz[4]; int dA[4];
    const char* b1s[4];
    const size_t w2delta = (const char*)g_w2H - (const char*)g_w1H;
#pragma unroll
    for (int i = 0; i < 4; i++) {
        int idx = tid + i * 256;
        int r = idx >> 3, c = idx & 7;
        dA[i] = sw_off(r, c);
        int tok = sg[r];
        asrc[i] = (tok >= 0) ? (const char*)(g_xH + (size_t)tok * D_DIM + c * 8)
                             : (const char*)g_xH;
        asz[i] = (tok >= 0) ? 16 : 0;
        b1s[i] = (const char*)(g_w1H + ((size_t)e * H_DIM + bn0 + r) * D_DIM + c * 8);
    }

#define U_LOAD(KT) do {                                                         \
    const int _s = (KT) % 3;                                                    \
    const uint32_t _b = sb + _s * STAGE_BYTES;                                  \
    const int _k = (KT) * (BKW * 2);                                            \
    _Pragma("unroll") for (int i = 0; i < 4; i++) {                             \
        cp16(_b + dA[i], asrc[i] + _k, asz[i]);                                 \
        cp16(_b + 16384 + dA[i], b1s[i] + _k, 16);                              \
        cp16(_b + 32768 + dA[i], b1s[i] + w2delta + _k, 16);                    \
    } } while (0)

    U_LOAD(0); CP_COMMIT;
    U_LOAD(1); CP_COMMIT;

    float cu[4][4][4], cv[4][4][4];
#pragma unroll
    for (int a = 0; a < 4; a++)
#pragma unroll
        for (int b = 0; b < 4; b++)
#pragma unroll
            for (int c = 0; c < 4; c++) { cu[a][b][c] = 0.0f; cv[a][b][c] = 0.0f; }

    for (int kt = 0; kt < UP_NK; kt++) {
        cp_wait<1>(); __syncthreads();
        if (kt + 2 < UP_NK) U_LOAD(kt + 2);
        CP_COMMIT;
        const uint32_t At  = sb + (kt % 3) * STAGE_BYTES;
        const uint32_t B1t = At + 16384;
        const uint32_t B2t = At + 32768;
#pragma unroll
        for (int ks = 0; ks < 4; ks++) {
            uint32_t a[4][4];
#pragma unroll
            for (int mi = 0; mi < 4; mi++) {
                int r = wm * 64 + mi * 16 + (lane & 15);
                int c = ks * 2 + (lane >> 4);
                ldsm4(a[mi][0], a[mi][1], a[mi][2], a[mi][3], At + sw_off(r, c));
            }
#pragma unroll
            for (int bj = 0; bj < 2; bj++) {
                int r = wn * 32 + bj * 16 + ((lane >> 4) << 3) + (lane & 7);
                int c = ks * 2 + ((lane >> 3) & 1);
                int off = sw_off(r, c);
                uint32_t q0, q1, q2, q3;
                ldsm4(q0, q1, q2, q3, B1t + off);
                { uint32_t b[2] = {q0, q1};
#pragma unroll
                  for (int mi = 0; mi < 4; mi++) mma16816(cu[mi][2 * bj], a[mi], b); }
                { uint32_t b[2] = {q2, q3};
#pragma unroll
                  for (int mi = 0; mi < 4; mi++) mma16816(cu[mi][2 * bj + 1], a[mi], b); }
                ldsm4(q0, q1, q2, q3, B2t + off);
                { uint32_t b[2] = {q0, q1};
#pragma unroll
                  for (int mi = 0; mi < 4; mi++) mma16816(cv[mi][2 * bj], a[mi], b); }
                { uint32_t b[2] = {q2, q3};
#pragma unroll
                  for (int mi = 0; mi < 4; mi++) mma16816(cv[mi][2 * bj + 1], a[mi], b); }
            }
        }
    }
#undef U_LOAD

    // epilogue: h = silu(u)*v -> fp16 hi -> g_hH
#pragma unroll
    for (int mi = 0; mi < 4; mi++) {
#pragma unroll
        for (int nj = 0; nj < 4; nj++) {
            int r0 = m0 + wm * 64 + mi * 16 + (lane >> 2);
            int col = bn0 + wn * 32 + nj * 8 + (lane & 3) * 2;
#pragma unroll
            for (int h = 0; h < 2; h++) {
                int r = r0 + 8 * h;
                float f0 = silu_f(cu[mi][nj][2 * h])     * cv[mi][nj][2 * h];
                float f1 = silu_f(cu[mi][nj][2 * h + 1]) * cv[mi][nj][2 * h + 1];
                __half2 hh = __floats2half2_rn(f0, f1);
                *(__half2*)(g_hH + (size_t)r * H_DIM + col) = hh;
            }
        }
    }
}

// ---------------- K5: down GEMM ----------------------------------------------
// block 128M x 256N, 8 warps (2m x 4n), warp 64x64. K = 2048 (hi only).
__global__ void __launch_bounds__(256, 1) gemm_down_mma() {
    const int e = g_tile_expert[blockIdx.y];
    if (e < 0) return;
    extern __shared__ char raw[];
    char* dsm = (char*)(((uintptr_t)raw + 1023) & ~(uintptr_t)1023);
    const int tid = threadIdx.x;
    const int m0 = blockIdx.y * BM;
    const int bn0 = blockIdx.x * 256;
    const uint32_t sb = smem_u32(dsm);
    const int lane = tid & 31, wid = tid >> 5;
    const int wm = wid & 1, wn = wid >> 1;

    const char* asrc[4]; int dA[4];
    const char* bsrc[8]; int dB[8];
#pragma unroll
    for (int i = 0; i < 4; i++) {
        int idx = tid + i * 256;
        int r = idx >> 3, c = idx & 7;
        dA[i] = sw_off(r, c);
        asrc[i] = (const char*)(g_hH + (size_t)(m0 + r) * H_DIM + c * 8);
    }
#pragma unroll
    for (int i = 0; i < 8; i++) {
        int idx = tid + i * 256;
        int r = idx >> 3, c = idx & 7;
        dB[i] = sw_off(r, c);
        bsrc[i] = (const char*)(g_w3H + ((size_t)e * D_DIM + bn0 + r) * H_DIM + c * 8);
    }

#define D_LOAD(KT) do {                                                         \
    const int _s = (KT) % 3;                                                    \
    const uint32_t _b = sb + _s * STAGE_BYTES;                                  \
    const long _k = (long)(KT) * (BKW * 2);                                     \
    _Pragma("unroll") for (int i = 0; i < 4; i++)                               \
        cp16(_b + dA[i], asrc[i] + _k, 16);                                     \
    _Pragma("unroll") for (int i = 0; i < 8; i++)                               \
        cp16(_b + 16384 + dB[i], bsrc[i] + _k, 16);                             \
    } while (0)

    D_LOAD(0); CP_COMMIT;
    D_LOAD(1); CP_COMMIT;

    float acc[4][8][4];
#pragma unroll
    for (int a = 0; a < 4; a++)
#pragma unroll
        for (int b = 0; b < 8; b++)
#pragma unroll
            for (int c = 0; c < 4; c++) acc[a][b][c] = 0.0f;

    for (int kt = 0; kt < DN_NK; kt++) {
        cp_wait<1>(); __syncthreads();
        if (kt + 2 < DN_NK) D_LOAD(kt + 2);
        CP_COMMIT;
        const uint32_t At = sb + (kt % 3) * STAGE_BYTES;
        const uint32_t Bt = At + 16384;
#pragma unroll
        for (int ks = 0; ks < 4; ks++) {
            uint32_t a[4][4];
#pragma unroll
            for (int mi = 0; mi < 4; mi++) {
                int r = wm * 64 + mi * 16 + (lane & 15);
                int c = ks * 2 + (lane >> 4);
                ldsm4(a[mi][0], a[mi][1], a[mi][2], a[mi][3], At + sw_off(r, c));
            }
#pragma unroll
            for (int bj = 0; bj < 4; bj++) {
                int r = wn * 64 + bj * 16 + ((lane >> 4) << 3) + (lane & 7);
                int c = ks * 2 + ((lane >> 3) & 1);
                uint32_t q0, q1, q2, q3;
                ldsm4(q0, q1, q2, q3, Bt + sw_off(r, c));
                { uint32_t b[2] = {q0, q1};
#pragma unroll
                  for (int mi = 0; mi < 4; mi++) mma16816(acc[mi][2 * bj], a[mi], b); }
                { uint32_t b[2] = {q2, q3};
#pragma unroll
                  for (int mi = 0; mi < 4; mi++) mma16816(acc[mi][2 * bj + 1], a[mi], b); }
            }
        }
    }
#undef D_LOAD

#pragma unroll
    for (int mi = 0; mi < 4; mi++) {
#pragma unroll
        for (int nj = 0; nj < 8; nj++) {
            int r0 = m0 + wm * 64 + mi * 16 + (lane >> 2);
            int col = bn0 + wn * 64 + nj * 8 + (lane & 3) * 2;
            float2 lo = make_float2(acc[mi][nj][0], acc[mi][nj][1]);
            float2 hi = make_float2(acc[mi][nj][2], acc[mi][nj][3]);
            *(float2*)(g_y + (size_t)r0 * D_DIM + col)       = lo;
            *(float2*)(g_y + (size_t)(r0 + 8) * D_DIM + col) = hi;
        }
    }
}

// ---------------- K6: combine -------------------------------------------------
__global__ void combine_kernel(float* __restrict__ out, int T) {
    const int nq = D_DIM / 4;
    int idx = blockIdx.x * blockDim.x + threadIdx.x;
    if (idx >= T * nq) return;
    int t = idx / nq;
    int dq = idx - t * nq;
    int r0 = g_row_of[2 * t];
    int r1 = g_row_of[2 * t + 1];
    float p0 = g_probs[2 * t];
    float p1 = g_probs[2 * t + 1];
    float4 y0 = *(const float4*)&g_y[(size_t)r0 * D_DIM + dq * 4];
    float4 y1 = *(const float4*)&g_y[(size_t)r1 * D_DIM + dq * 4];
    float4 o;
    o.x = p0 * y0.x + p1 * y1.x;
    o.y = p0 * y0.y + p1 * y1.y;
    o.z = p0 * y0.z + p1 * y1.z;
    o.w = p0 * y0.w + p1 * y1.w;
    *(float4*)&out[(size_t)t * D_DIM + dq * 4] = o;
}

// ---------------- launch -------------------------------------------------------
extern "C" void kernel_launch(void* const* d_in, const int* in_sizes, int n_in,
                              void* d_out, int out_size) {
    const float* x  = (const float*)d_in[0];
    const float* gw = (const float*)d_in[1];
    const float* w1 = (const float*)d_in[2];
    const float* w2 = (const float*)d_in[3];
    const float* w3 = (const float*)d_in[4];
    float* out = (float*)d_out;

    int T = in_sizes[0] / D_DIM;
    if (T > T_MAX) T = T_MAX;
    int m_tiles = (2 * T) / BM + E_NUM;
    if (m_tiles > MAX_TILES) m_tiles = MAX_TILES;

    cudaFuncSetAttribute(gemm_up_mma,   cudaFuncAttributeMaxDynamicSharedMemorySize, GEMM_SMEM);
    cudaFuncSetAttribute(gemm_down_mma, cudaFuncAttributeMaxDynamicSharedMemorySize, GEMM_SMEM);

    init_kernel<<<1, 32>>>();
    router_kernel<<<(T + 7) / 8, 256>>>(x, gw, T);
    scan_kernel<<<1, 32>>>(m_tiles);
    build_kernel<<<m_tiles, BM>>>();

    long xt4 = (long)T * D_DIM / 4;
    conv_x_kernel<<<(int)((xt4 + 255) / 256), 256>>>(x, xt4);
    long w12t4 = (long)E_NUM * H_DIM * D_DIM / 4;
    conv_w_hi_kernel<<<(int)((w12t4 + 255) / 256), 256>>>(w1, 0, w12t4);
    conv_w_hi_kernel<<<(int)((w12t4 + 255) / 256), 256>>>(w2, 1, w12t4);
    long w3t4 = (long)E_NUM * D_DIM * H_DIM / 4;
    conv_w_hi_kernel<<<(int)((w3t4 + 255) / 256), 256>>>(w3, 2, w3t4);

    gemm_up_mma<<<dim3(H_DIM / 128, m_tiles), 256, GEMM_SMEM>>>();
    gemm_down_mma<<<dim3(D_DIM / 256, m_tiles), 256, GEMM_SMEM>>>();
    combine_kernel<<<(T * (D_DIM / 4) + 255) / 256, 256>>>(out, T);
}

// round 7
// speedup vs baseline: 7.0752x; 1.0394x over previous
#include <cuda_runtime.h>
#include <cuda_fp16.h>
#include <cstdint>

#define D_DIM 1024
#define H_DIM 2048
#define E_NUM 8
#define T_MAX 4096
#define BM 128
#define MAX_TILES 72
#define MAX_ROWS  (MAX_TILES * BM)

#define BKW 64                /* fp16 K elems per stage */
#define UP_NK 16              /* D/BKW */
#define DN_NK 32              /* H/BKW */
#define STAGE_BYTES 49152     /* per-stage smem (up: A16+B16+B16; down: A16+B32) */
#define NSTAGE 4
#define GEMM_SMEM (NSTAGE * STAGE_BYTES + 1024)   /* 197632 */

// ---------------- device-global scratch ------------------------------------
__device__ int   g_counts[E_NUM];
__device__ int   g_offsets[E_NUM + 1];
__device__ int   g_tile_expert[MAX_TILES];
__device__ int   g_list[E_NUM * T_MAX];
__device__ float g_probs[2 * T_MAX];
__device__ int   g_gather[MAX_ROWS];
__device__ int   g_row_of[2 * T_MAX];
__device__ __half g_xH [(size_t)T_MAX * D_DIM];                 // hi only
__device__ __half g_w1H[(size_t)E_NUM * H_DIM * D_DIM];         // hi only
__device__ __half g_w2H[(size_t)E_NUM * H_DIM * D_DIM];         // hi only
__device__ __half g_w3H[(size_t)E_NUM * D_DIM * H_DIM];         // hi only
__device__ __half g_hH [(size_t)MAX_ROWS * H_DIM];              // hi only
__device__ float g_y[(size_t)MAX_ROWS * D_DIM];

// ---------------- helpers ----------------------------------------------------
__device__ __forceinline__ uint32_t smem_u32(const void* p) {
    uint32_t a;
    asm("{ .reg .u64 t; cvta.to.shared.u64 t, %1; cvt.u32.u64 %0, t; }"
        : "=r"(a) : "l"(p));
    return a;
}
__device__ __forceinline__ void ldsm4(uint32_t& r0, uint32_t& r1, uint32_t& r2,
                                      uint32_t& r3, uint32_t addr) {
    asm volatile("ldmatrix.sync.aligned.m8n8.x4.shared.b16 {%0,%1,%2,%3}, [%4];"
                 : "=r"(r0), "=r"(r1), "=r"(r2), "=r"(r3) : "r"(addr));
}
__device__ __forceinline__ void mma16816(float* c, const uint32_t* a,
                                         const uint32_t* b) {
    asm volatile(
        "mma.sync.aligned.m16n8k16.row.col.f32.f16.f16.f32 "
        "{%0,%1,%2,%3},{%4,%5,%6,%7},{%8,%9},{%0,%1,%2,%3};"
        : "+f"(c[0]), "+f"(c[1]), "+f"(c[2]), "+f"(c[3])
        : "r"(a[0]), "r"(a[1]), "r"(a[2]), "r"(a[3]), "r"(b[0]), "r"(b[1]));
}
__device__ __forceinline__ void cp16(uint32_t dst, const void* src, int srcsize) {
    asm volatile("cp.async.cg.shared.global [%0], [%1], 16, %2;"
                 :: "r"(dst), "l"(src), "r"(srcsize) : "memory");
}
#define CP_COMMIT asm volatile("cp.async.commit_group;" ::: "memory")
template <int N>
__device__ __forceinline__ void cp_wait() {
    asm volatile("cp.async.wait_group %0;" :: "n"(N) : "memory");
}
__device__ __forceinline__ float silu_f(float v) { return v / (1.0f + __expf(-v)); }
__device__ __forceinline__ int sw_off(int r, int c) {
    return r * 128 + ((c ^ (r & 7)) << 4);
}

// ---------------- K0: init ----------------------------------------------------
__global__ void init_kernel() {
    if (threadIdx.x < E_NUM) g_counts[threadIdx.x] = 0;
}

// ---------------- K1: router + fused x->fp16 conversion -----------------------
__global__ void router_kernel(const float* __restrict__ x,
                              const float* __restrict__ gw, int T) {
    int warp = blockIdx.x * (blockDim.x >> 5) + (threadIdx.x >> 5);
    int lane = threadIdx.x & 31;
    if (warp >= T) return;
    const float* xr = x + (size_t)warp * D_DIM;
    __half* xh = g_xH + (size_t)warp * D_DIM;

    float acc[E_NUM];
#pragma unroll
    for (int e = 0; e < E_NUM; e++) acc[e] = 0.0f;

#pragma unroll
    for (int i = 0; i < D_DIM / 128; i++) {       // 8 iters, float4 per lane
        int d = i * 128 + lane * 4;
        float4 xv = *(const float4*)(xr + d);
        __half2 h0 = __floats2half2_rn(xv.x, xv.y);
        __half2 h1 = __floats2half2_rn(xv.z, xv.w);
        *(uint2*)(xh + d) = make_uint2(*(uint32_t*)&h0, *(uint32_t*)&h1);
#pragma unroll
        for (int e = 0; e < E_NUM; e++) {
            float4 gv = *(const float4*)(gw + e * D_DIM + d);
            acc[e] += xv.x * gv.x + xv.y * gv.y + xv.z * gv.z + xv.w * gv.w;
        }
    }
#pragma unroll
    for (int e = 0; e < E_NUM; e++) {
#pragma unroll
        for (int off = 16; off > 0; off >>= 1)
            acc[e] += __shfl_xor_sync(0xFFFFFFFFu, acc[e], off);
    }
    if (lane == 0) {
        int e0 = 0; float s0 = acc[0];
#pragma unroll
        for (int e = 1; e < E_NUM; e++) if (acc[e] > s0) { s0 = acc[e]; e0 = e; }
        int e1 = -1; float s1 = -3.4e38f;
#pragma unroll
        for (int e = 0; e < E_NUM; e++)
            if (e != e0 && acc[e] > s1) { s1 = acc[e]; e1 = e; }
        float x1 = __expf(s1 - s0);
        float inv = 1.0f / (1.0f + x1);
        int t = warp;
        g_probs[2 * t] = inv;
        g_probs[2 * t + 1] = x1 * inv;
        int j0 = atomicAdd(&g_counts[e0], 1);
        g_list[e0 * T_MAX + j0] = (t << 1);
        int j1 = atomicAdd(&g_counts[e1], 1);
        g_list[e1 * T_MAX + j1] = (t << 1) | 1;
    }
}

// ---------------- K2/K3: scan + build -----------------------------------------
__global__ void scan_kernel(int m_tiles_max) {
    if (threadIdx.x != 0 || blockIdx.x != 0) return;
    int off = 0, nt = 0;
    for (int e = 0; e < E_NUM; e++) {
        g_offsets[e] = off;
        int c = g_counts[e];
        int te = (c + BM - 1) / BM;
        for (int k = 0; k < te; k++) g_tile_expert[nt++] = e;
        off += te * BM;
    }
    g_offsets[E_NUM] = off;
    for (; nt < m_tiles_max; nt++) g_tile_expert[nt] = -1;
}

__global__ void build_kernel() {
    int tile = blockIdx.x;
    int e = g_tile_expert[tile];
    int r = tile * BM + threadIdx.x;
    if (e < 0) { g_gather[r] = -1; return; }
    int j = r - g_offsets[e];
    if (j < g_counts[e]) {
        int entry = g_list[e * T_MAX + j];
        g_gather[r] = entry >> 1;
        g_row_of[entry] = r;
    } else {
        g_gather[r] = -1;
    }
}

// ---------------- weight conversion: all three tensors, one launch ------------
__global__ void conv_w_all_kernel(const float* __restrict__ w1,
                                  const float* __restrict__ w2,
                                  const float* __restrict__ w3, long n4) {
    long i = blockIdx.x * (long)blockDim.x + threadIdx.x;
    if (i >= 3 * n4) return;
    const float* src;
    __half* dst;
    long j;
    if (i < n4)           { src = w1; dst = g_w1H; j = i; }
    else if (i < 2 * n4)  { src = w2; dst = g_w2H; j = i - n4; }
    else                  { src = w3; dst = g_w3H; j = i - 2 * n4; }
    long eb = j * 4;
    float4 v = *(const float4*)(src + eb);
    __half2 h0 = __floats2half2_rn(v.x, v.y);
    __half2 h1 = __floats2half2_rn(v.z, v.w);
    *(uint2*)(dst + eb) = make_uint2(*(uint32_t*)&h0, *(uint32_t*)&h1);
}

// ---------------- K4: up GEMM --------------------------------------------------
// block 128M x 128N (both u and v), 8 warps (2m x 4n), warp 64x32 per matrix.
// 4-stage cp.async pipeline, 2-deep prefetch.
__global__ void __launch_bounds__(256, 1) gemm_up_mma() {
    const int e = g_tile_expert[blockIdx.y];
    if (e < 0) return;
    extern __shared__ char raw[];
    char* dsm = (char*)(((uintptr_t)raw + 1023) & ~(uintptr_t)1023);
    __shared__ int sg[BM];
    const int tid = threadIdx.x;
    const int m0 = blockIdx.y * BM;
    const int bn0 = blockIdx.x * 128;
    if (tid < BM) sg[tid] = g_gather[m0 + tid];
    __syncthreads();
    const uint32_t sb = smem_u32(dsm);
    const int lane = tid & 31, wid = tid >> 5;
    const int wm = wid & 1, wn = wid >> 1;

    const char* asrc[4]; int asz[4]; int dA[4];
    const char* b1s[4];
    const size_t w2delta = (const char*)g_w2H - (const char*)g_w1H;
#pragma unroll
    for (int i = 0; i < 4; i++) {
        int idx = tid + i * 256;
        int r = idx >> 3, c = idx & 7;
        dA[i] = sw_off(r, c);
        int tok = sg[r];
        asrc[i] = (tok >= 0) ? (const char*)(g_xH + (size_t)tok * D_DIM + c * 8)
                             : (const char*)g_xH;
        asz[i] = (tok >= 0) ? 16 : 0;
        b1s[i] = (const char*)(g_w1H + ((size_t)e * H_DIM + bn0 + r) * D_DIM + c * 8);
    }

#define U_LOAD(KT) do {                                                         \
    const int _s = (KT) % NSTAGE;                                               \
    const uint32_t _b = sb + _s * STAGE_BYTES;                                  \
    const int _k = (KT) * (BKW * 2);                                            \
    _Pragma("unroll") for (int i = 0; i < 4; i++) {                             \
        cp16(_b + dA[i], asrc[i] + _k, asz[i]);                                 \
        cp16(_b + 16384 + dA[i], b1s[i] + _k, 16);                              \
        cp16(_b + 32768 + dA[i], b1s[i] + w2delta + _k, 16);                    \
    } } while (0)

    U_LOAD(0); CP_COMMIT;
    U_LOAD(1); CP_COMMIT;
    U_LOAD(2); CP_COMMIT;

    float cu[4][4][4], cv[4][4][4];
#pragma unroll
    for (int a = 0; a < 4; a++)
#pragma unroll
        for (int b = 0; b < 4; b++)
#pragma unroll
            for (int c = 0; c < 4; c++) { cu[a][b][c] = 0.0f; cv[a][b][c] = 0.0f; }

    for (int kt = 0; kt < UP_NK; kt++) {
        cp_wait<2>(); __syncthreads();
        if (kt + 3 < UP_NK) U_LOAD(kt + 3);
        CP_COMMIT;
        const uint32_t At  = sb + (kt % NSTAGE) * STAGE_BYTES;
        const uint32_t B1t = At + 16384;
        const uint32_t B2t = At + 32768;
#pragma unroll
        for (int ks = 0; ks < 4; ks++) {
            uint32_t a[4][4];
#pragma unroll
            for (int mi = 0; mi < 4; mi++) {
                int r = wm * 64 + mi * 16 + (lane & 15);
                int c = ks * 2 + (lane >> 4);
                ldsm4(a[mi][0], a[mi][1], a[mi][2], a[mi][3], At + sw_off(r, c));
            }
#pragma unroll
            for (int bj = 0; bj < 2; bj++) {
                int r = wn * 32 + bj * 16 + ((lane >> 4) << 3) + (lane & 7);
                int c = ks * 2 + ((lane >> 3) & 1);
                int off = sw_off(r, c);
                uint32_t q0, q1, q2, q3;
                ldsm4(q0, q1, q2, q3, B1t + off);
                { uint32_t b[2] = {q0, q1};
#pragma unroll
                  for (int mi = 0; mi < 4; mi++) mma16816(cu[mi][2 * bj], a[mi], b); }
                { uint32_t b[2] = {q2, q3};
#pragma unroll
                  for (int mi = 0; mi < 4; mi++) mma16816(cu[mi][2 * bj + 1], a[mi], b); }
                ldsm4(q0, q1, q2, q3, B2t + off);
                { uint32_t b[2] = {q0, q1};
#pragma unroll
                  for (int mi = 0; mi < 4; mi++) mma16816(cv[mi][2 * bj], a[mi], b); }
                { uint32_t b[2] = {q2, q3};
#pragma unroll
                  for (int mi = 0; mi < 4; mi++) mma16816(cv[mi][2 * bj + 1], a[mi], b); }
            }
        }
    }
#undef U_LOAD

    // epilogue: h = silu(u)*v -> fp16 hi -> g_hH
#pragma unroll
    for (int mi = 0; mi < 4; mi++) {
#pragma unroll
        for (int nj = 0; nj < 4; nj++) {
            int r0 = m0 + wm * 64 + mi * 16 + (lane >> 2);
            int col = bn0 + wn * 32 + nj * 8 + (lane & 3) * 2;
#pragma unroll
            for (int h = 0; h < 2; h++) {
                int r = r0 + 8 * h;
                float f0 = silu_f(cu[mi][nj][2 * h])     * cv[mi][nj][2 * h];
                float f1 = silu_f(cu[mi][nj][2 * h + 1]) * cv[mi][nj][2 * h + 1];
                __half2 hh = __floats2half2_rn(f0, f1);
                *(__half2*)(g_hH + (size_t)r * H_DIM + col) = hh;
            }
        }
    }
}

// ---------------- K5: down GEMM ------------------------------------------------
// block 128M x 256N, 8 warps (2m x 4n), warp 64x64. K = 2048. 4-stage pipeline.
__global__ void __launch_bounds__(256, 1) gemm_down_mma() {
    const int e = g_tile_expert[blockIdx.y];
    if (e < 0) return;
    extern __shared__ char raw[];
    char* dsm = (char*)(((uintptr_t)raw + 1023) & ~(uintptr_t)1023);
    const int tid = threadIdx.x;
    const int m0 = blockIdx.y * BM;
    const int bn0 = blockIdx.x * 256;
    const uint32_t sb = smem_u32(dsm);
    const int lane = tid & 31, wid = tid >> 5;
    const int wm = wid & 1, wn = wid >> 1;

    const char* asrc[4]; int dA[4];
    const char* bsrc[8]; int dB[8];
#pragma unroll
    for (int i = 0; i < 4; i++) {
        int idx = tid + i * 256;
        int r = idx >> 3, c = idx & 7;
        dA[i] = sw_off(r, c);
        asrc[i] = (const char*)(g_hH + (size_t)(m0 + r) * H_DIM + c * 8);
    }
#pragma unroll
    for (int i = 0; i < 8; i++) {
        int idx = tid + i * 256;
        int r = idx >> 3, c = idx & 7;
        dB[i] = sw_off(r, c);
        bsrc[i] = (const char*)(g_w3H + ((size_t)e * D_DIM + bn0 + r) * H_DIM + c * 8);
    }

#define D_LOAD(KT) do {                                                         \
    const int _s = (KT) % NSTAGE;                                               \
    const uint32_t _b = sb + _s * STAGE_BYTES;                                  \
    const long _k = (long)(KT) * (BKW * 2);                                     \
    _Pragma("unroll") for (int i = 0; i < 4; i++)                               \
        cp16(_b + dA[i], asrc[i] + _k, 16);                                     \
    _Pragma("unroll") for (int i = 0; i < 8; i++)                               \
        cp16(_b + 16384 + dB[i], bsrc[i] + _k, 16);                             \
    } while (0)

    D_LOAD(0); CP_COMMIT;
    D_LOAD(1); CP_COMMIT;
    D_LOAD(2); CP_COMMIT;

    float acc[4][8][4];
#pragma unroll
    for (int a = 0; a < 4; a++)
#pragma unroll
        for (int b = 0; b < 8; b++)
#pragma unroll
            for (int c = 0; c < 4; c++) acc[a][b][c] = 0.0f;

    for (int kt = 0; kt < DN_NK; kt++) {
        cp_wait<2>(); __syncthreads();
        if (kt + 3 < DN_NK) D_LOAD(kt + 3);
        CP_COMMIT;
        const uint32_t At = sb + (kt % NSTAGE) * STAGE_BYTES;
        const uint32_t Bt = At + 16384;
#pragma unroll
        for (int ks = 0; ks < 4; ks++) {
            uint32_t a[4][4];
#pragma unroll
            for (int mi = 0; mi < 4; mi++) {
                int r = wm * 64 + mi * 16 + (lane & 15);
                int c = ks * 2 + (lane >> 4);
                ldsm4(a[mi][0], a[mi][1], a[mi][2], a[mi][3], At + sw_off(r, c));
            }
#pragma unroll
            for (int bj = 0; bj < 4; bj++) {
                int r = wn * 64 + bj * 16 + ((lane >> 4) << 3) + (lane & 7);
                int c = ks * 2 + ((lane >> 3) & 1);
                uint32_t q0, q1, q2, q3;
                ldsm4(q0, q1, q2, q3, Bt + sw_off(r, c));
                { uint32_t b[2] = {q0, q1};
#pragma unroll
                  for (int mi = 0; mi < 4; mi++) mma16816(acc[mi][2 * bj], a[mi], b); }
                { uint32_t b[2] = {q2, q3};
#pragma unroll
                  for (int mi = 0; mi < 4; mi++) mma16816(acc[mi][2 * bj + 1], a[mi], b); }
            }
        }
    }
#undef D_LOAD

#pragma unroll
    for (int mi = 0; mi < 4; mi++) {
#pragma unroll
        for (int nj = 0; nj < 8; nj++) {
            int r0 = m0 + wm * 64 + mi * 16 + (lane >> 2);
            int col = bn0 + wn * 64 + nj * 8 + (lane & 3) * 2;
            float2 lo = make_float2(acc[mi][nj][0], acc[mi][nj][1]);
            float2 hi = make_float2(acc[mi][nj][2], acc[mi][nj][3]);
            *(float2*)(g_y + (size_t)r0 * D_DIM + col)       = lo;
            *(float2*)(g_y + (size_t)(r0 + 8) * D_DIM + col) = hi;
        }
    }
}

// ---------------- K6: combine ---------------------------------------------------
__global__ void combine_kernel(float* __restrict__ out, int T) {
    const int nq = D_DIM / 4;
    int idx = blockIdx.x * blockDim.x + threadIdx.x;
    if (idx >= T * nq) return;
    int t = idx / nq;
    int dq = idx - t * nq;
    int r0 = g_row_of[2 * t];
    int r1 = g_row_of[2 * t + 1];
    float p0 = g_probs[2 * t];
    float p1 = g_probs[2 * t + 1];
    float4 y0 = *(const float4*)&g_y[(size_t)r0 * D_DIM + dq * 4];
    float4 y1 = *(const float4*)&g_y[(size_t)r1 * D_DIM + dq * 4];
    float4 o;
    o.x = p0 * y0.x + p1 * y1.x;
    o.y = p0 * y0.y + p1 * y1.y;
    o.z = p0 * y0.z + p1 * y1.z;
    o.w = p0 * y0.w + p1 * y1.w;
    *(float4*)&out[(size_t)t * D_DIM + dq * 4] = o;
}

// ---------------- launch ---------------------------------------------------------
extern "C" void kernel_launch(void* const* d_in, const int* in_sizes, int n_in,
                              void* d_out, int out_size) {
    const float* x  = (const float*)d_in[0];
    const float* gw = (const float*)d_in[1];
    const float* w1 = (const float*)d_in[2];
    const float* w2 = (const float*)d_in[3];
    const float* w3 = (const float*)d_in[4];
    float* out = (float*)d_out;

    int T = in_sizes[0] / D_DIM;
    if (T > T_MAX) T = T_MAX;
    int m_tiles = (2 * T) / BM + E_NUM;
    if (m_tiles > MAX_TILES) m_tiles = MAX_TILES;

    cudaFuncSetAttribute(gemm_up_mma,   cudaFuncAttributeMaxDynamicSharedMemorySize, GEMM_SMEM);
    cudaFuncSetAttribute(gemm_down_mma, cudaFuncAttributeMaxDynamicSharedMemorySize, GEMM_SMEM);

    init_kernel<<<1, 32>>>();
    router_kernel<<<(T + 7) / 8, 256>>>(x, gw, T);
    scan_kernel<<<1, 32>>>(m_tiles);
    build_kernel<<<m_tiles, BM>>>();

    long n4 = (long)E_NUM * H_DIM * D_DIM / 4;   // same for w1/w2/w3
    conv_w_all_kernel<<<(int)((3 * n4 + 255) / 256), 256>>>(w1, w2, w3, n4);

    gemm_up_mma<<<dim3(H_DIM / 128, m_tiles), 256, GEMM_SMEM>>>();
    gemm_down_mma<<<dim3(D_DIM / 256, m_tiles), 256, GEMM_SMEM>>>();
    combine_kernel<<<(T * (D_DIM / 4) + 255) / 256, 256>>>(out, T);
}